// round 2
// baseline (speedup 1.0000x reference)
#include <cuda_runtime.h>
#include <cuda_bf16.h>

#define D_MODEL 1024
#define NHEAD   16
#define DK      64
#define BATCH   2
#define SEQ     2048
#define M_TOT   (BATCH*SEQ)   // 4096

typedef unsigned long long ULL;

// Scratch (allocation-free rule: __device__ globals)
__device__ float g_q[(size_t)BATCH*SEQ*D_MODEL];
__device__ float g_k[(size_t)BATCH*SEQ*D_MODEL];
__device__ float g_v[(size_t)BATCH*SEQ*D_MODEL];
__device__ float g_o[(size_t)BATCH*SEQ*D_MODEL];

// ---------------- packed f32x2 helpers (Blackwell) ----------------
__device__ __forceinline__ ULL f2pack(float lo, float hi) {
    ULL d;
    asm("mov.b64 %0, {%1, %2};" : "=l"(d)
        : "r"(__float_as_uint(lo)), "r"(__float_as_uint(hi)));
    return d;
}
__device__ __forceinline__ void f2unpack(ULL d, float& lo, float& hi) {
    unsigned int a, b;
    asm("mov.b64 {%0, %1}, %2;" : "=r"(a), "=r"(b) : "l"(d));
    lo = __uint_as_float(a); hi = __uint_as_float(b);
}
__device__ __forceinline__ ULL ffma2(ULL a, ULL b, ULL c) {
    ULL d;
    asm("fma.rn.f32x2 %0, %1, %2, %3;" : "=l"(d) : "l"(a), "l"(b), "l"(c));
    return d;
}
__device__ __forceinline__ ULL fadd2(ULL a, ULL b) {
    ULL d;
    asm("add.rn.f32x2 %0, %1, %2;" : "=l"(d) : "l"(a), "l"(b));
    return d;
}
__device__ __forceinline__ ULL fmul2(ULL a, ULL b) {
    ULL d;
    asm("mul.rn.f32x2 %0, %1, %2;" : "=l"(d) : "l"(a), "l"(b));
    return d;
}

// ---------------------------------------------------------------------------
// SGEMM: C[M,N] = A[M,K] * B[N,K]^T  (unchanged: measured 61 TF/s ~ fp32 peak)
// ---------------------------------------------------------------------------
#define BM 64
#define BN 64
#define BK 16

__global__ __launch_bounds__(256) void sgemm_abT(
    const float* __restrict__ A,
    const float* __restrict__ B0, const float* __restrict__ B1, const float* __restrict__ B2,
    float* __restrict__ C0, float* __restrict__ C1, float* __restrict__ C2,
    int M, int N, int K)
{
    const float* B; float* C;
    if (blockIdx.z == 0)      { B = B0; C = C0; }
    else if (blockIdx.z == 1) { B = B1; C = C1; }
    else                      { B = B2; C = C2; }

    __shared__ float As[BK][BM + 1];
    __shared__ float Bs[BK][BN + 1];

    const int tid = threadIdx.x;
    const int tx = tid & 15;
    const int ty = tid >> 4;
    const int row0 = blockIdx.y * BM;
    const int col0 = blockIdx.x * BN;

    float acc[4][4] = {};

    for (int k0 = 0; k0 < K; k0 += BK) {
        #pragma unroll
        for (int i = 0; i < 4; i++) {
            int idx = tid + i * 256;
            int r  = idx >> 4;
            int kk = idx & 15;
            As[kk][r] = A[(size_t)(row0 + r) * K + k0 + kk];
            Bs[kk][r] = B[(size_t)(col0 + r) * K + k0 + kk];
        }
        __syncthreads();

        #pragma unroll
        for (int kk = 0; kk < BK; kk++) {
            float a[4], b[4];
            #pragma unroll
            for (int i = 0; i < 4; i++) a[i] = As[kk][ty * 4 + i];
            #pragma unroll
            for (int j = 0; j < 4; j++) b[j] = Bs[kk][tx * 4 + j];
            #pragma unroll
            for (int i = 0; i < 4; i++)
                #pragma unroll
                for (int j = 0; j < 4; j++)
                    acc[i][j] += a[i] * b[j];
        }
        __syncthreads();
    }

    #pragma unroll
    for (int i = 0; i < 4; i++)
        #pragma unroll
        for (int j = 0; j < 4; j++)
            C[(size_t)(row0 + ty * 4 + i) * N + col0 + tx * 4 + j] = acc[i][j];
}

// ---------------------------------------------------------------------------
// RoPE in-place on Q and K (unchanged)
// ---------------------------------------------------------------------------
__global__ void rope_kernel(float* __restrict__ q, float* __restrict__ k,
                            const int* __restrict__ pos)
{
    int idx = blockIdx.x * blockDim.x + threadIdx.x;
    if (idx >= BATCH * SEQ * NHEAD * (DK / 2)) return;
    int i  = idx & 31;
    int h  = (idx >> 5) & 15;
    int bs = idx >> 9;
    int p  = pos[bs];

    float inv = __expf(-(float)(2 * i) * (9.210340371976184f / 64.0f));
    float ang = (float)p * inv;
    float sn, cs;
    sincosf(ang, &sn, &cs);

    size_t off = (size_t)bs * D_MODEL + h * DK + 2 * i;
    float e = q[off], o = q[off + 1];
    q[off]     = e * cs - o * sn;
    q[off + 1] = e * sn + o * cs;
    e = k[off]; o = k[off + 1];
    k[off]     = e * cs - o * sn;
    k[off + 1] = e * sn + o * cs;
}

// ---------------------------------------------------------------------------
// Causal flash attention v2:
//  - 2 threads per query (DK split in halves), score joined via shfl.xor(1)
//  - packed f32x2 FMA for QK and PV (pairs come free from 128-bit smem loads)
//  - BR=128 queries/block, 256 threads, BC=32 keys per smem tile
//  Register budget/thread: qr 32 + oacc 32 + s 32 + misc ~ 110 -> good occupancy
// ---------------------------------------------------------------------------
#define BR 128
#define BC 32

__global__ __launch_bounds__(256) void flash_kernel(
    const float* __restrict__ q, const float* __restrict__ k,
    const float* __restrict__ v, float* __restrict__ o)
{
    const int bh = blockIdx.y;
    const int b  = bh >> 4;
    const int h  = bh & 15;
    const int q0 = blockIdx.x * BR;
    const int tid  = threadIdx.x;
    const int ql   = tid >> 1;       // local query 0..127
    const int half = tid & 1;        // which 32-dim half of DK
    const int qi   = q0 + ql;

    __shared__ float Ks[BC][DK];
    __shared__ float Vs[BC][DK];

    // Load this thread's half of the query row, prescaled by 1/sqrt(64), packed.
    ULL qr[16];
    {
        const float4* qb = (const float4*)(q + ((size_t)(b * SEQ + qi)) * D_MODEL
                                           + h * DK + half * 32);
        #pragma unroll
        for (int d4 = 0; d4 < 8; d4++) {
            float4 t = qb[d4];
            qr[2*d4]   = f2pack(t.x * 0.125f, t.y * 0.125f);
            qr[2*d4+1] = f2pack(t.z * 0.125f, t.w * 0.125f);
        }
    }

    ULL oacc[16];
    #pragma unroll
    for (int i = 0; i < 16; i++) oacc[i] = 0ULL;
    float m = -1e30f, l = 0.f;

    const int kend = q0 + BR;   // causal: keys beyond the block's last query never needed
    for (int k0 = 0; k0 < kend; k0 += BC) {
        __syncthreads();
        #pragma unroll
        for (int it = 0; it < 2; it++) {
            int i  = tid + it * 256;           // over BC*DK/4 = 512 float4 slots
            int r  = i >> 4;                   // 0..31
            int d4 = i & 15;                   // 0..15
            size_t go = ((size_t)(b * SEQ + k0 + r)) * D_MODEL + h * DK + d4 * 4;
            ((float4*)&Ks[r][0])[d4] = *(const float4*)(k + go);
            ((float4*)&Vs[r][0])[d4] = *(const float4*)(v + go);
        }
        __syncthreads();

        // --- scores ---
        float s[BC];
        float tmax = -1e30f;
        #pragma unroll
        for (int j = 0; j < BC; j++) {
            const ulonglong2* kj = (const ulonglong2*)&Ks[j][half * 32];
            ULL a0 = 0ULL, a1 = 0ULL, a2 = 0ULL, a3 = 0ULL;
            #pragma unroll
            for (int i = 0; i < 4; i++) {
                ulonglong2 ka = kj[2*i];
                ulonglong2 kb = kj[2*i+1];
                a0 = ffma2(qr[4*i+0], ka.x, a0);
                a1 = ffma2(qr[4*i+1], ka.y, a1);
                a2 = ffma2(qr[4*i+2], kb.x, a2);
                a3 = ffma2(qr[4*i+3], kb.y, a3);
            }
            ULL aa = fadd2(fadd2(a0, a1), fadd2(a2, a3));
            float lo, hi; f2unpack(aa, lo, hi);
            float part = lo + hi;
            float sv = part + __shfl_xor_sync(0xffffffffu, part, 1);
            if (k0 + j > qi) sv = -1e30f;
            s[j] = sv;
            tmax = fmaxf(tmax, sv);
        }

        float mnew = fmaxf(m, tmax);
        float corr = __expf(m - mnew);
        l *= corr;
        ULL corr2 = f2pack(corr, corr);
        #pragma unroll
        for (int i = 0; i < 16; i++) oacc[i] = fmul2(oacc[i], corr2);

        // --- probs * V ---
        #pragma unroll
        for (int j = 0; j < BC; j++) {
            float p = __expf(s[j] - mnew);
            l += p;
            ULL pp = f2pack(p, p);
            const ulonglong2* vj = (const ulonglong2*)&Vs[j][half * 32];
            #pragma unroll
            for (int i = 0; i < 8; i++) {
                ulonglong2 vv = vj[i];
                oacc[2*i]   = ffma2(pp, vv.x, oacc[2*i]);
                oacc[2*i+1] = ffma2(pp, vv.y, oacc[2*i+1]);
            }
        }
        m = mnew;
    }

    const float invl = 1.0f / l;
    ULL invl2 = f2pack(invl, invl);
    ulonglong2* ob = (ulonglong2*)(o + ((size_t)(b * SEQ + qi)) * D_MODEL
                                   + h * DK + half * 32);
    #pragma unroll
    for (int i = 0; i < 8; i++) {
        ulonglong2 t;
        t.x = fmul2(oacc[2*i],   invl2);
        t.y = fmul2(oacc[2*i+1], invl2);
        ob[i] = t;
    }
}

// ---------------------------------------------------------------------------
// Launch
// ---------------------------------------------------------------------------
extern "C" void kernel_launch(void* const* d_in, const int* in_sizes, int n_in,
                              void* d_out, int out_size)
{
    const float* x  = (const float*)d_in[0];
    const float* Wq = (const float*)d_in[1];
    const float* Wk = (const float*)d_in[2];
    const float* Wv = (const float*)d_in[3];
    const float* Wo = (const float*)d_in[4];
    const int*   tp = (const int*)d_in[5];
    float* out = (float*)d_out;

    float *qp, *kp, *vp, *op;
    cudaGetSymbolAddress((void**)&qp, g_q);
    cudaGetSymbolAddress((void**)&kp, g_k);
    cudaGetSymbolAddress((void**)&vp, g_v);
    cudaGetSymbolAddress((void**)&op, g_o);

    // 1) QKV projections
    dim3 g1(D_MODEL / BN, M_TOT / BM, 3);
    sgemm_abT<<<g1, 256>>>(x, Wq, Wk, Wv, qp, kp, vp, M_TOT, D_MODEL, D_MODEL);

    // 2) RoPE on Q and K
    int npairs = BATCH * SEQ * NHEAD * (DK / 2);
    rope_kernel<<<(npairs + 255) / 256, 256>>>(qp, kp, tp);

    // 3) Causal flash attention
    flash_kernel<<<dim3(SEQ / BR, BATCH * NHEAD), 256>>>(qp, kp, vp, op);

    // 4) Output projection
    dim3 g2(D_MODEL / BN, M_TOT / BM, 1);
    sgemm_abT<<<g2, 256>>>(op, Wo, Wo, Wo, out, out, out, M_TOT, D_MODEL, D_MODEL);
}

// round 4
// speedup vs baseline: 1.2924x; 1.2924x over previous
#include <cuda_runtime.h>
#include <cuda_bf16.h>

#define D_MODEL 1024
#define NHEAD   16
#define DK      64
#define BATCH   2
#define SEQ     2048
#define M_TOT   (BATCH*SEQ)   // 4096

// Scratch (allocation-free rule: __device__ globals)
__device__ float g_q[(size_t)BATCH*SEQ*D_MODEL];
__device__ float g_k[(size_t)BATCH*SEQ*D_MODEL];
__device__ float g_v[(size_t)BATCH*SEQ*D_MODEL];
__device__ float g_o[(size_t)BATCH*SEQ*D_MODEL];

// ---------------------------------------------------------------------------
// SGEMM: C[M,N] = A[M,K] * B[N,K]^T  (measured 62 TF/s ~ 82% fp32 peak; keep)
// ---------------------------------------------------------------------------
#define BM 64
#define BN 64
#define BK 16

__global__ __launch_bounds__(256) void sgemm_abT(
    const float* __restrict__ A,
    const float* __restrict__ B0, const float* __restrict__ B1, const float* __restrict__ B2,
    float* __restrict__ C0, float* __restrict__ C1, float* __restrict__ C2,
    int M, int N, int K)
{
    const float* B; float* C;
    if (blockIdx.z == 0)      { B = B0; C = C0; }
    else if (blockIdx.z == 1) { B = B1; C = C1; }
    else                      { B = B2; C = C2; }

    __shared__ float As[BK][BM + 1];
    __shared__ float Bs[BK][BN + 1];

    const int tid = threadIdx.x;
    const int tx = tid & 15;
    const int ty = tid >> 4;
    const int row0 = blockIdx.y * BM;
    const int col0 = blockIdx.x * BN;

    float acc[4][4] = {};

    for (int k0 = 0; k0 < K; k0 += BK) {
        #pragma unroll
        for (int i = 0; i < 4; i++) {
            int idx = tid + i * 256;
            int r  = idx >> 4;
            int kk = idx & 15;
            As[kk][r] = A[(size_t)(row0 + r) * K + k0 + kk];
            Bs[kk][r] = B[(size_t)(col0 + r) * K + k0 + kk];
        }
        __syncthreads();

        #pragma unroll
        for (int kk = 0; kk < BK; kk++) {
            float a[4], b[4];
            #pragma unroll
            for (int i = 0; i < 4; i++) a[i] = As[kk][ty * 4 + i];
            #pragma unroll
            for (int j = 0; j < 4; j++) b[j] = Bs[kk][tx * 4 + j];
            #pragma unroll
            for (int i = 0; i < 4; i++)
                #pragma unroll
                for (int j = 0; j < 4; j++)
                    acc[i][j] += a[i] * b[j];
        }
        __syncthreads();
    }

    #pragma unroll
    for (int i = 0; i < 4; i++)
        #pragma unroll
        for (int j = 0; j < 4; j++)
            C[(size_t)(row0 + ty * 4 + i) * N + col0 + tx * 4 + j] = acc[i][j];
}

// ---------------------------------------------------------------------------
// RoPE in-place on Q and K (unchanged)
// ---------------------------------------------------------------------------
__global__ void rope_kernel(float* __restrict__ q, float* __restrict__ k,
                            const int* __restrict__ pos)
{
    int idx = blockIdx.x * blockDim.x + threadIdx.x;
    if (idx >= BATCH * SEQ * NHEAD * (DK / 2)) return;
    int i  = idx & 31;
    int h  = (idx >> 5) & 15;
    int bs = idx >> 9;
    int p  = pos[bs];

    float inv = __expf(-(float)(2 * i) * (9.210340371976184f / 64.0f));
    float ang = (float)p * inv;
    float sn, cs;
    sincosf(ang, &sn, &cs);

    size_t off = (size_t)bs * D_MODEL + h * DK + 2 * i;
    float e = q[off], o = q[off + 1];
    q[off]     = e * cs - o * sn;
    q[off + 1] = e * sn + o * cs;
    e = k[off]; o = k[off + 1];
    k[off]     = e * cs - o * sn;
    k[off + 1] = e * sn + o * cs;
}

// ---------------------------------------------------------------------------
// Causal flash attention v3 — SGEMM-structured.
// Block: 64 queries x 64 keys per tile, 256 threads as 16(ty rows) x 16(tx),
// 4x4 register micro-tiles for both S=Q.K^T and O+=P.V.
// Smem (dynamic, 49920B): QsT[64][65] (dim-major), KV[64][65]
// (K dim-major, later V key-major in the same buffer), Ps[64][65] (row-major).
// ---------------------------------------------------------------------------
#define FBR 64
#define FBC 64
#define FPAD 65
#define QS_OFF 0
#define KV_OFF (64*FPAD)
#define PS_OFF (2*64*FPAD)
#define FLASH_SMEM_BYTES (3*64*FPAD*4)

__global__ __launch_bounds__(256) void flash_kernel(
    const float* __restrict__ q, const float* __restrict__ k,
    const float* __restrict__ v, float* __restrict__ o)
{
    extern __shared__ float sm[];
    float* Qs = sm + QS_OFF;   // Qs[dim][row]
    float* KV = sm + KV_OFF;   // phase 1: K[dim][col]; phase 2: V[key][dim]
    float* Ps = sm + PS_OFF;   // Ps[row][key]

    const int bh = blockIdx.y;
    const int b  = bh >> 4;
    const int h  = bh & 15;
    const int qt = (int)gridDim.x - 1 - (int)blockIdx.x;  // long blocks first
    const int q0 = qt * FBR;
    const int tid = threadIdx.x;
    const int tx = tid & 15;
    const int ty = tid >> 4;
    const int ty4 = ty * 4, tx4 = tx * 4;

    // ---- load Q tile transposed (dim-major), prescaled by 1/8 ----
    {
        const size_t base = ((size_t)(b * SEQ + q0)) * D_MODEL + h * DK;
        #pragma unroll
        for (int it = 0; it < 4; it++) {
            int i  = tid + it * 256;     // 1024 float4 slots
            int r  = i >> 4;             // 0..63 query row
            int d4 = i & 15;             // 0..15
            float4 t = *(const float4*)(q + base + (size_t)r * D_MODEL + d4 * 4);
            Qs[(d4*4+0) * FPAD + r] = t.x * 0.125f;
            Qs[(d4*4+1) * FPAD + r] = t.y * 0.125f;
            Qs[(d4*4+2) * FPAD + r] = t.z * 0.125f;
            Qs[(d4*4+3) * FPAD + r] = t.w * 0.125f;
        }
    }

    float oacc[4][4];
    #pragma unroll
    for (int i = 0; i < 4; i++)
        #pragma unroll
        for (int j = 0; j < 4; j++) oacc[i][j] = 0.f;
    float m[4], l[4];
    #pragma unroll
    for (int i = 0; i < 4; i++) { m[i] = -1e30f; l[i] = 0.f; }

    const int kend = q0 + FBR;          // causal tile skip
    for (int k0 = 0; k0 < kend; k0 += FBC) {
        // ---- load K tile transposed (dim-major) ----
        __syncthreads();                // prev O-phase reads of KV done
        {
            const size_t base = ((size_t)(b * SEQ + k0)) * D_MODEL + h * DK;
            #pragma unroll
            for (int it = 0; it < 4; it++) {
                int i  = tid + it * 256;
                int r  = i >> 4;         // key index 0..63
                int d4 = i & 15;
                float4 t = *(const float4*)(k + base + (size_t)r * D_MODEL + d4 * 4);
                KV[(d4*4+0) * FPAD + r] = t.x;
                KV[(d4*4+1) * FPAD + r] = t.y;
                KV[(d4*4+2) * FPAD + r] = t.z;
                KV[(d4*4+3) * FPAD + r] = t.w;
            }
        }
        __syncthreads();

        // ---- S = Q.K^T (4x4 micro-tile, contraction over 64 dims) ----
        float s[4][4];
        #pragma unroll
        for (int i = 0; i < 4; i++)
            #pragma unroll
            for (int j = 0; j < 4; j++) s[i][j] = 0.f;

        #pragma unroll 8
        for (int kk = 0; kk < DK; kk++) {
            float a[4], bb[4];
            #pragma unroll
            for (int i = 0; i < 4; i++) a[i]  = Qs[kk * FPAD + ty4 + i];
            #pragma unroll
            for (int j = 0; j < 4; j++) bb[j] = KV[kk * FPAD + tx4 + j];
            #pragma unroll
            for (int i = 0; i < 4; i++)
                #pragma unroll
                for (int j = 0; j < 4; j++)
                    s[i][j] += a[i] * bb[j];
        }

        // ---- causal mask (only the diagonal tile needs it) ----
        if (k0 + FBC > q0) {
            #pragma unroll
            for (int i = 0; i < 4; i++)
                #pragma unroll
                for (int j = 0; j < 4; j++)
                    if (k0 + tx4 + j > q0 + ty4 + i) s[i][j] = -1e30f;
        }

        // ---- online softmax (row stats reduced over the 16 tx lanes) ----
        float corr[4];
        #pragma unroll
        for (int i = 0; i < 4; i++) {
            float tmax = fmaxf(fmaxf(s[i][0], s[i][1]), fmaxf(s[i][2], s[i][3]));
            #pragma unroll
            for (int off = 1; off < 16; off <<= 1)
                tmax = fmaxf(tmax, __shfl_xor_sync(0xffffffffu, tmax, off));
            float mnew = fmaxf(m[i], tmax);
            corr[i] = __expf(m[i] - mnew);
            float rs = 0.f;
            #pragma unroll
            for (int j = 0; j < 4; j++) {
                s[i][j] = __expf(s[i][j] - mnew);
                rs += s[i][j];
            }
            #pragma unroll
            for (int off = 1; off < 16; off <<= 1)
                rs += __shfl_xor_sync(0xffffffffu, rs, off);
            l[i] = l[i] * corr[i] + rs;
            m[i] = mnew;
            // write P tile (row-major)
            #pragma unroll
            for (int j = 0; j < 4; j++)
                Ps[(ty4 + i) * FPAD + tx4 + j] = s[i][j];
            // rescale O accumulator
            #pragma unroll
            for (int j = 0; j < 4; j++) oacc[i][j] *= corr[i];
        }

        // ---- load V tile (key-major) into the K buffer ----
        __syncthreads();                // QK reads of KV done; Ps visible
        {
            const size_t base = ((size_t)(b * SEQ + k0)) * D_MODEL + h * DK;
            #pragma unroll
            for (int it = 0; it < 4; it++) {
                int i  = tid + it * 256;
                int r  = i >> 4;
                int d4 = i & 15;
                float4 t = *(const float4*)(v + base + (size_t)r * D_MODEL + d4 * 4);
                KV[r * FPAD + d4*4 + 0] = t.x;
                KV[r * FPAD + d4*4 + 1] = t.y;
                KV[r * FPAD + d4*4 + 2] = t.z;
                KV[r * FPAD + d4*4 + 3] = t.w;
            }
        }
        __syncthreads();

        // ---- O += P.V (contraction over 64 keys; dims = tx4..tx4+3) ----
        #pragma unroll 8
        for (int kk = 0; kk < FBC; kk++) {
            float a[4], bb[4];
            #pragma unroll
            for (int i = 0; i < 4; i++) a[i]  = Ps[(ty4 + i) * FPAD + kk];
            #pragma unroll
            for (int j = 0; j < 4; j++) bb[j] = KV[kk * FPAD + tx4 + j];
            #pragma unroll
            for (int i = 0; i < 4; i++)
                #pragma unroll
                for (int j = 0; j < 4; j++)
                    oacc[i][j] += a[i] * bb[j];
        }
    }

    // ---- write O ----
    #pragma unroll
    for (int i = 0; i < 4; i++) {
        float invl = 1.0f / l[i];
        float4 t;
        t.x = oacc[i][0] * invl;
        t.y = oacc[i][1] * invl;
        t.z = oacc[i][2] * invl;
        t.w = oacc[i][3] * invl;
        *(float4*)(o + ((size_t)(b * SEQ + q0 + ty4 + i)) * D_MODEL + h * DK + tx4) = t;
    }
}

// ---------------------------------------------------------------------------
// Launch
// ---------------------------------------------------------------------------
extern "C" void kernel_launch(void* const* d_in, const int* in_sizes, int n_in,
                              void* d_out, int out_size)
{
    const float* x  = (const float*)d_in[0];
    const float* Wq = (const float*)d_in[1];
    const float* Wk = (const float*)d_in[2];
    const float* Wv = (const float*)d_in[3];
    const float* Wo = (const float*)d_in[4];
    const int*   tp = (const int*)d_in[5];
    float* out = (float*)d_out;

    float *qp, *kp, *vp, *op;
    cudaGetSymbolAddress((void**)&qp, g_q);
    cudaGetSymbolAddress((void**)&kp, g_k);
    cudaGetSymbolAddress((void**)&vp, g_v);
    cudaGetSymbolAddress((void**)&op, g_o);

    // 1) QKV projections
    dim3 g1(D_MODEL / BN, M_TOT / BM, 3);
    sgemm_abT<<<g1, 256>>>(x, Wq, Wk, Wv, qp, kp, vp, M_TOT, D_MODEL, D_MODEL);

    // 2) RoPE on Q and K
    int npairs = BATCH * SEQ * NHEAD * (DK / 2);
    rope_kernel<<<(npairs + 255) / 256, 256>>>(qp, kp, tp);

    // 3) Causal flash attention (SGEMM-structured)
    cudaFuncSetAttribute(flash_kernel,
                         cudaFuncAttributeMaxDynamicSharedMemorySize,
                         FLASH_SMEM_BYTES);
    flash_kernel<<<dim3(SEQ / FBR, BATCH * NHEAD), 256, FLASH_SMEM_BYTES>>>(qp, kp, vp, op);

    // 4) Output projection
    dim3 g2(D_MODEL / BN, M_TOT / BM, 1);
    sgemm_abT<<<g2, 256>>>(op, Wo, Wo, Wo, out, out, out, M_TOT, D_MODEL, D_MODEL);
}

// round 7
// speedup vs baseline: 1.5945x; 1.2338x over previous
#include <cuda_runtime.h>
#include <cuda_bf16.h>

#define D_MODEL 1024
#define NHEAD   16
#define DK      64
#define BATCH   2
#define SEQ     2048
#define M_TOT   (BATCH*SEQ)   // 4096

// Scratch (allocation-free rule: __device__ globals)
__device__ float g_q[(size_t)BATCH*SEQ*D_MODEL];
__device__ float g_k[(size_t)BATCH*SEQ*D_MODEL];
__device__ float g_v[(size_t)BATCH*SEQ*D_MODEL];
__device__ float g_o[(size_t)BATCH*SEQ*D_MODEL];

// ---------------------------------------------------------------------------
// SGEMM: C[M,N] = A[M,K] * B[N,K]^T  (measured 62 TF/s ~ 82% fp32 peak; keep)
// ---------------------------------------------------------------------------
#define BM 64
#define BN 64
#define BK 16

__global__ __launch_bounds__(256) void sgemm_abT(
    const float* __restrict__ A,
    const float* __restrict__ B0, const float* __restrict__ B1, const float* __restrict__ B2,
    float* __restrict__ C0, float* __restrict__ C1, float* __restrict__ C2,
    int M, int N, int K)
{
    const float* B; float* C;
    if (blockIdx.z == 0)      { B = B0; C = C0; }
    else if (blockIdx.z == 1) { B = B1; C = C1; }
    else                      { B = B2; C = C2; }

    __shared__ float As[BK][BM + 1];
    __shared__ float Bs[BK][BN + 1];

    const int tid = threadIdx.x;
    const int tx = tid & 15;
    const int ty = tid >> 4;
    const int row0 = blockIdx.y * BM;
    const int col0 = blockIdx.x * BN;

    float acc[4][4] = {};

    for (int k0 = 0; k0 < K; k0 += BK) {
        #pragma unroll
        for (int i = 0; i < 4; i++) {
            int idx = tid + i * 256;
            int r  = idx >> 4;
            int kk = idx & 15;
            As[kk][r] = A[(size_t)(row0 + r) * K + k0 + kk];
            Bs[kk][r] = B[(size_t)(col0 + r) * K + k0 + kk];
        }
        __syncthreads();

        #pragma unroll
        for (int kk = 0; kk < BK; kk++) {
            float a[4], b[4];
            #pragma unroll
            for (int i = 0; i < 4; i++) a[i] = As[kk][ty * 4 + i];
            #pragma unroll
            for (int j = 0; j < 4; j++) b[j] = Bs[kk][tx * 4 + j];
            #pragma unroll
            for (int i = 0; i < 4; i++)
                #pragma unroll
                for (int j = 0; j < 4; j++)
                    acc[i][j] += a[i] * b[j];
        }
        __syncthreads();
    }

    #pragma unroll
    for (int i = 0; i < 4; i++)
        #pragma unroll
        for (int j = 0; j < 4; j++)
            C[(size_t)(row0 + ty * 4 + i) * N + col0 + tx * 4 + j] = acc[i][j];
}

// ---------------------------------------------------------------------------
// RoPE in-place on Q and K (unchanged)
// ---------------------------------------------------------------------------
__global__ void rope_kernel(float* __restrict__ q, float* __restrict__ k,
                            const int* __restrict__ pos)
{
    int idx = blockIdx.x * blockDim.x + threadIdx.x;
    if (idx >= BATCH * SEQ * NHEAD * (DK / 2)) return;
    int i  = idx & 31;
    int h  = (idx >> 5) & 15;
    int bs = idx >> 9;
    int p  = pos[bs];

    float inv = __expf(-(float)(2 * i) * (9.210340371976184f / 64.0f));
    float ang = (float)p * inv;
    float sn, cs;
    sincosf(ang, &sn, &cs);

    size_t off = (size_t)bs * D_MODEL + h * DK + 2 * i;
    float e = q[off], o = q[off + 1];
    q[off]     = e * cs - o * sn;
    q[off + 1] = e * sn + o * cs;
    e = k[off]; o = k[off + 1];
    k[off]     = e * cs - o * sn;
    k[off + 1] = e * sn + o * cs;
}

// ---------------------------------------------------------------------------
// Flash attention v4b — tensor cores (mma.sync m16n8k16 bf16, f32 accum),
// 3-term split (AhBh + AlBh + AhBl) for near-fp32 accuracy.
// Block: 256 threads = 8 warps; BR=128 queries (m16 per warp), BC=64 keys.
// Static smem: Kh/Kl row-major [64 keys][72 bf16], Vh/Vl dim-major [64][72].
// ---------------------------------------------------------------------------
#define FP 72   // bf16 pitch (144B rows -> conflict-free b-frag LDS)

__device__ __forceinline__ void mma16816(float* c,
    unsigned a0, unsigned a1, unsigned a2, unsigned a3,
    unsigned b0, unsigned b1)
{
    asm volatile(
        "mma.sync.aligned.m16n8k16.row.col.f32.bf16.bf16.f32 "
        "{%0,%1,%2,%3},{%4,%5,%6,%7},{%8,%9},{%0,%1,%2,%3};\n"
        : "+f"(c[0]), "+f"(c[1]), "+f"(c[2]), "+f"(c[3])
        : "r"(a0), "r"(a1), "r"(a2), "r"(a3), "r"(b0), "r"(b1));
}

// split (x,y) into packed bf16x2 hi + residual lo (x in low half)
__device__ __forceinline__ void split2(float x, float y, unsigned& h, unsigned& l)
{
    __nv_bfloat162 hh = __floats2bfloat162_rn(x, y);
    float rx = x - __bfloat162float(hh.x);
    float ry = y - __bfloat162float(hh.y);
    __nv_bfloat162 ll = __floats2bfloat162_rn(rx, ry);
    h = *reinterpret_cast<unsigned*>(&hh);
    l = *reinterpret_cast<unsigned*>(&ll);
}

__global__ __launch_bounds__(256) void flash_mma_kernel(
    const float* __restrict__ q, const float* __restrict__ k,
    const float* __restrict__ v, float* __restrict__ o)
{
    __shared__ __align__(16) __nv_bfloat16 Kh[64 * FP];
    __shared__ __align__(16) __nv_bfloat16 Kl[64 * FP];
    __shared__ __align__(16) __nv_bfloat16 Vh[64 * FP];
    __shared__ __align__(16) __nv_bfloat16 Vl[64 * FP];

    const int bh = blockIdx.y;
    const int b  = bh >> 4;
    const int h  = bh & 15;
    const int qt = (int)gridDim.x - 1 - (int)blockIdx.x;   // long blocks first
    const int q0 = qt * 128;
    const int tid  = threadIdx.x;
    const int warp = tid >> 5;
    const int lane = tid & 31;
    const int g    = lane >> 2;       // 0..7
    const int tig  = lane & 3;        // 0..3
    const int wr0  = q0 + warp * 16;  // this warp's first query row (seq coord)

    // ---- load Q A-fragments (hi/lo), prescaled by 1/sqrt(64) ----
    unsigned qh[4][4], ql[4][4];
    {
        const float* qr0 = q + ((size_t)(b * SEQ + wr0 + g)) * D_MODEL + h * DK;
        const float* qr1 = qr0 + (size_t)8 * D_MODEL;
        #pragma unroll
        for (int kt = 0; kt < 4; kt++) {
            int d0 = kt * 16 + 2 * tig;
            float2 x;
            x = *(const float2*)(qr0 + d0);
            split2(x.x * 0.125f, x.y * 0.125f, qh[kt][0], ql[kt][0]);
            x = *(const float2*)(qr1 + d0);
            split2(x.x * 0.125f, x.y * 0.125f, qh[kt][1], ql[kt][1]);
            x = *(const float2*)(qr0 + d0 + 8);
            split2(x.x * 0.125f, x.y * 0.125f, qh[kt][2], ql[kt][2]);
            x = *(const float2*)(qr1 + d0 + 8);
            split2(x.x * 0.125f, x.y * 0.125f, qh[kt][3], ql[kt][3]);
        }
    }

    float oa[8][4];
    #pragma unroll
    for (int nj = 0; nj < 8; nj++)
        #pragma unroll
        for (int e = 0; e < 4; e++) oa[nj][e] = 0.f;
    float m0 = -1e30f, m1 = -1e30f, l0 = 0.f, l1 = 0.f;

    const int kend = q0 + 128;        // causal tile skip
    for (int k0 = 0; k0 < kend; k0 += 64) {
        // ---- stage K (row-major) and V (dim-major) as bf16 hi/lo ----
        __syncthreads();
        #pragma unroll
        for (int it = 0; it < 4; it++) {
            int idx = tid + it * 256;        // 1024 float4 slots = 64x64 floats
            int r   = idx >> 4;              // key 0..63
            int d4  = idx & 15;              // dim/4
            size_t go = ((size_t)(b * SEQ + k0 + r)) * D_MODEL + h * DK + d4 * 4;
            float4 tk = *(const float4*)(k + go);
            unsigned h01, l01, h23, l23;
            split2(tk.x, tk.y, h01, l01);
            split2(tk.z, tk.w, h23, l23);
            int ko = r * FP + 4 * d4;
            *(unsigned*)&Kh[ko]     = h01;
            *(unsigned*)&Kh[ko + 2] = h23;
            *(unsigned*)&Kl[ko]     = l01;
            *(unsigned*)&Kl[ko + 2] = l23;

            float4 tv = *(const float4*)(v + go);
            float xs[4] = {tv.x, tv.y, tv.z, tv.w};
            #pragma unroll
            for (int jj = 0; jj < 4; jj++) {
                __nv_bfloat16 hv = __float2bfloat16_rn(xs[jj]);
                __nv_bfloat16 lv = __float2bfloat16_rn(xs[jj] - __bfloat162float(hv));
                Vh[(4 * d4 + jj) * FP + r] = hv;
                Vl[(4 * d4 + jj) * FP + r] = lv;
            }
        }
        __syncthreads();

        // ---- S = Q.K^T : 8 n-tiles x 4 k-tiles x 3 terms ----
        float s[8][4];
        #pragma unroll
        for (int nj = 0; nj < 8; nj++) {
            s[nj][0] = s[nj][1] = s[nj][2] = s[nj][3] = 0.f;
            const int krow = (nj * 8 + g) * FP;
            #pragma unroll
            for (int kt = 0; kt < 4; kt++) {
                int off = krow + kt * 16 + 2 * tig;
                unsigned bh0 = *(const unsigned*)&Kh[off];
                unsigned bh1 = *(const unsigned*)&Kh[off + 8];
                unsigned bl0 = *(const unsigned*)&Kl[off];
                unsigned bl1 = *(const unsigned*)&Kl[off + 8];
                mma16816(s[nj], qh[kt][0], qh[kt][1], qh[kt][2], qh[kt][3], bh0, bh1);
                mma16816(s[nj], ql[kt][0], ql[kt][1], ql[kt][2], ql[kt][3], bh0, bh1);
                mma16816(s[nj], qh[kt][0], qh[kt][1], qh[kt][2], qh[kt][3], bl0, bl1);
            }
        }

        // ---- causal mask (only needed near the diagonal for this warp) ----
        if (k0 + 63 > wr0 + g) {
            int r0 = wr0 + g, r1 = r0 + 8;
            #pragma unroll
            for (int nj = 0; nj < 8; nj++) {
                int c = k0 + nj * 8 + 2 * tig;
                if (c     > r0) s[nj][0] = -1e30f;
                if (c + 1 > r0) s[nj][1] = -1e30f;
                if (c     > r1) s[nj][2] = -1e30f;
                if (c + 1 > r1) s[nj][3] = -1e30f;
            }
        }

        // ---- online softmax (rows g and g+8; reduce over tig lanes) ----
        float rm0 = -1e30f, rm1 = -1e30f;
        #pragma unroll
        for (int nj = 0; nj < 8; nj++) {
            rm0 = fmaxf(rm0, fmaxf(s[nj][0], s[nj][1]));
            rm1 = fmaxf(rm1, fmaxf(s[nj][2], s[nj][3]));
        }
        rm0 = fmaxf(rm0, __shfl_xor_sync(0xffffffffu, rm0, 1));
        rm0 = fmaxf(rm0, __shfl_xor_sync(0xffffffffu, rm0, 2));
        rm1 = fmaxf(rm1, __shfl_xor_sync(0xffffffffu, rm1, 1));
        rm1 = fmaxf(rm1, __shfl_xor_sync(0xffffffffu, rm1, 2));

        float mn0 = fmaxf(m0, rm0), mn1 = fmaxf(m1, rm1);
        float corr0 = __expf(m0 - mn0), corr1 = __expf(m1 - mn1);
        float rs0 = 0.f, rs1 = 0.f;
        #pragma unroll
        for (int nj = 0; nj < 8; nj++) {
            s[nj][0] = __expf(s[nj][0] - mn0);
            s[nj][1] = __expf(s[nj][1] - mn0);
            s[nj][2] = __expf(s[nj][2] - mn1);
            s[nj][3] = __expf(s[nj][3] - mn1);
            rs0 += s[nj][0] + s[nj][1];
            rs1 += s[nj][2] + s[nj][3];
        }
        rs0 += __shfl_xor_sync(0xffffffffu, rs0, 1);
        rs0 += __shfl_xor_sync(0xffffffffu, rs0, 2);
        rs1 += __shfl_xor_sync(0xffffffffu, rs1, 1);
        rs1 += __shfl_xor_sync(0xffffffffu, rs1, 2);
        l0 = l0 * corr0 + rs0;
        l1 = l1 * corr1 + rs1;
        m0 = mn0; m1 = mn1;

        // rescale O accumulator
        #pragma unroll
        for (int nj = 0; nj < 8; nj++) {
            oa[nj][0] *= corr0; oa[nj][1] *= corr0;
            oa[nj][2] *= corr1; oa[nj][3] *= corr1;
        }

        // ---- convert P to A-fragments (hi/lo): QK C-frags ARE PV A-frags ----
        unsigned pah[4][4], pal[4][4];
        #pragma unroll
        for (int kt = 0; kt < 4; kt++) {
            split2(s[2*kt][0],   s[2*kt][1],   pah[kt][0], pal[kt][0]);
            split2(s[2*kt][2],   s[2*kt][3],   pah[kt][1], pal[kt][1]);
            split2(s[2*kt+1][0], s[2*kt+1][1], pah[kt][2], pal[kt][2]);
            split2(s[2*kt+1][2], s[2*kt+1][3], pah[kt][3], pal[kt][3]);
        }

        // ---- O += P.V : 8 n-tiles (dims) x 4 k-tiles (keys) x 3 terms ----
        #pragma unroll
        for (int nj = 0; nj < 8; nj++) {
            const int vrow = (nj * 8 + g) * FP;
            #pragma unroll
            for (int kt = 0; kt < 4; kt++) {
                int off = vrow + kt * 16 + 2 * tig;
                unsigned bh0 = *(const unsigned*)&Vh[off];
                unsigned bh1 = *(const unsigned*)&Vh[off + 8];
                unsigned bl0 = *(const unsigned*)&Vl[off];
                unsigned bl1 = *(const unsigned*)&Vl[off + 8];
                mma16816(oa[nj], pah[kt][0], pah[kt][1], pah[kt][2], pah[kt][3], bh0, bh1);
                mma16816(oa[nj], pal[kt][0], pal[kt][1], pal[kt][2], pal[kt][3], bh0, bh1);
                mma16816(oa[nj], pah[kt][0], pah[kt][1], pah[kt][2], pah[kt][3], bl0, bl1);
            }
        }
    }

    // ---- write O ----
    {
        float inv0 = 1.0f / l0, inv1 = 1.0f / l1;
        float* or0 = o + ((size_t)(b * SEQ + wr0 + g)) * D_MODEL + h * DK;
        float* or1 = or0 + (size_t)8 * D_MODEL;
        #pragma unroll
        for (int nj = 0; nj < 8; nj++) {
            int d = nj * 8 + 2 * tig;
            *(float2*)(or0 + d) = make_float2(oa[nj][0] * inv0, oa[nj][1] * inv0);
            *(float2*)(or1 + d) = make_float2(oa[nj][2] * inv1, oa[nj][3] * inv1);
        }
    }
}

// ---------------------------------------------------------------------------
// Launch
// ---------------------------------------------------------------------------
extern "C" void kernel_launch(void* const* d_in, const int* in_sizes, int n_in,
                              void* d_out, int out_size)
{
    const float* x  = (const float*)d_in[0];
    const float* Wq = (const float*)d_in[1];
    const float* Wk = (const float*)d_in[2];
    const float* Wv = (const float*)d_in[3];
    const float* Wo = (const float*)d_in[4];
    const int*   tp = (const int*)d_in[5];
    float* out = (float*)d_out;

    float *qp, *kp, *vp, *op;
    cudaGetSymbolAddress((void**)&qp, g_q);
    cudaGetSymbolAddress((void**)&kp, g_k);
    cudaGetSymbolAddress((void**)&vp, g_v);
    cudaGetSymbolAddress((void**)&op, g_o);

    // 1) QKV projections
    dim3 g1(D_MODEL / BN, M_TOT / BM, 3);
    sgemm_abT<<<g1, 256>>>(x, Wq, Wk, Wv, qp, kp, vp, M_TOT, D_MODEL, D_MODEL);

    // 2) RoPE on Q and K
    int npairs = BATCH * SEQ * NHEAD * (DK / 2);
    rope_kernel<<<(npairs + 255) / 256, 256>>>(qp, kp, tp);

    // 3) Causal flash attention (tensor cores, split-bf16)
    flash_mma_kernel<<<dim3(SEQ / 128, BATCH * NHEAD), 256>>>(qp, kp, vp, op);

    // 4) Output projection
    dim3 g2(D_MODEL / BN, M_TOT / BM, 1);
    sgemm_abT<<<g2, 256>>>(op, Wo, Wo, Wo, out, out, out, M_TOT, D_MODEL, D_MODEL);
}

// round 8
// speedup vs baseline: 1.6575x; 1.0395x over previous
#include <cuda_runtime.h>
#include <cuda_bf16.h>

#define D_MODEL 1024
#define NHEAD   16
#define DK      64
#define BATCH   2
#define SEQ     2048
#define M_TOT   (BATCH*SEQ)   // 4096
#define NPAIRS  (M_TOT*D_MODEL/2)

// Scratch (allocation-free rule: __device__ globals)
__device__ float g_q[(size_t)BATCH*SEQ*D_MODEL];
__device__ float g_k[(size_t)BATCH*SEQ*D_MODEL];
__device__ float g_v[(size_t)BATCH*SEQ*D_MODEL];
__device__ float g_o[(size_t)BATCH*SEQ*D_MODEL];
// precomputed bf16 hi/lo splits
__device__ __nv_bfloat16 g_qh[(size_t)M_TOT*D_MODEL];
__device__ __nv_bfloat16 g_ql[(size_t)M_TOT*D_MODEL];
__device__ __nv_bfloat16 g_kh[(size_t)M_TOT*D_MODEL];
__device__ __nv_bfloat16 g_kl[(size_t)M_TOT*D_MODEL];
// V transposed per (b,h): [bh][dim][seq]
__device__ __nv_bfloat16 g_vth[(size_t)M_TOT*D_MODEL];
__device__ __nv_bfloat16 g_vtl[(size_t)M_TOT*D_MODEL];

// ---------------------------------------------------------------------------
// SGEMM: C[M,N] = A[M,K] * B[N,K]^T  (measured 62 TF/s ~ 82% fp32 peak; keep)
// ---------------------------------------------------------------------------
#define BM 64
#define BN 64
#define BK 16

__global__ __launch_bounds__(256) void sgemm_abT(
    const float* __restrict__ A,
    const float* __restrict__ B0, const float* __restrict__ B1, const float* __restrict__ B2,
    float* __restrict__ C0, float* __restrict__ C1, float* __restrict__ C2,
    int M, int N, int K)
{
    const float* B; float* C;
    if (blockIdx.z == 0)      { B = B0; C = C0; }
    else if (blockIdx.z == 1) { B = B1; C = C1; }
    else                      { B = B2; C = C2; }

    __shared__ float As[BK][BM + 1];
    __shared__ float Bs[BK][BN + 1];

    const int tid = threadIdx.x;
    const int tx = tid & 15;
    const int ty = tid >> 4;
    const int row0 = blockIdx.y * BM;
    const int col0 = blockIdx.x * BN;

    float acc[4][4] = {};

    for (int k0 = 0; k0 < K; k0 += BK) {
        #pragma unroll
        for (int i = 0; i < 4; i++) {
            int idx = tid + i * 256;
            int r  = idx >> 4;
            int kk = idx & 15;
            As[kk][r] = A[(size_t)(row0 + r) * K + k0 + kk];
            Bs[kk][r] = B[(size_t)(col0 + r) * K + k0 + kk];
        }
        __syncthreads();

        #pragma unroll
        for (int kk = 0; kk < BK; kk++) {
            float a[4], b[4];
            #pragma unroll
            for (int i = 0; i < 4; i++) a[i] = As[kk][ty * 4 + i];
            #pragma unroll
            for (int j = 0; j < 4; j++) b[j] = Bs[kk][tx * 4 + j];
            #pragma unroll
            for (int i = 0; i < 4; i++)
                #pragma unroll
                for (int j = 0; j < 4; j++)
                    acc[i][j] += a[i] * b[j];
        }
        __syncthreads();
    }

    #pragma unroll
    for (int i = 0; i < 4; i++)
        #pragma unroll
        for (int j = 0; j < 4; j++)
            C[(size_t)(row0 + ty * 4 + i) * N + col0 + tx * 4 + j] = acc[i][j];
}

// ---------------------------------------------------------------------------
// RoPE in-place on Q and K (unchanged)
// ---------------------------------------------------------------------------
__global__ void rope_kernel(float* __restrict__ q, float* __restrict__ k,
                            const int* __restrict__ pos)
{
    int idx = blockIdx.x * blockDim.x + threadIdx.x;
    if (idx >= BATCH * SEQ * NHEAD * (DK / 2)) return;
    int i  = idx & 31;
    int h  = (idx >> 5) & 15;
    int bs = idx >> 9;
    int p  = pos[bs];

    float inv = __expf(-(float)(2 * i) * (9.210340371976184f / 64.0f));
    float ang = (float)p * inv;
    float sn, cs;
    sincosf(ang, &sn, &cs);

    size_t off = (size_t)bs * D_MODEL + h * DK + 2 * i;
    float e = q[off], o = q[off + 1];
    q[off]     = e * cs - o * sn;
    q[off + 1] = e * sn + o * cs;
    e = k[off]; o = k[off + 1];
    k[off]     = e * cs - o * sn;
    k[off + 1] = e * sn + o * cs;
}

// ---------------------------------------------------------------------------
// bf16 hi/lo split helpers
// ---------------------------------------------------------------------------
__device__ __forceinline__ void split2(float x, float y, unsigned& h, unsigned& l)
{
    __nv_bfloat162 hh = __floats2bfloat162_rn(x, y);
    float rx = x - __bfloat162float(hh.x);
    float ry = y - __bfloat162float(hh.y);
    __nv_bfloat162 ll = __floats2bfloat162_rn(rx, ry);
    h = *reinterpret_cast<unsigned*>(&hh);
    l = *reinterpret_cast<unsigned*>(&ll);
}

// Q (scaled by 1/8) and K -> hi/lo bf16 pairs, same layout as source
__global__ void qk_split_kernel(const float* __restrict__ q, const float* __restrict__ k)
{
    int idx = blockIdx.x * blockDim.x + threadIdx.x;
    if (idx >= NPAIRS) return;
    unsigned* qh = reinterpret_cast<unsigned*>(g_qh);
    unsigned* ql = reinterpret_cast<unsigned*>(g_ql);
    unsigned* kh = reinterpret_cast<unsigned*>(g_kh);
    unsigned* kl = reinterpret_cast<unsigned*>(g_kl);
    float2 xq = ((const float2*)q)[idx];
    unsigned h, l;
    split2(xq.x * 0.125f, xq.y * 0.125f, h, l);
    qh[idx] = h; ql[idx] = l;
    float2 xk = ((const float2*)k)[idx];
    split2(xk.x, xk.y, h, l);
    kh[idx] = h; kl[idx] = l;
}

// V -> transposed per-(b,h) hi/lo bf16: vt[bh][d][s]; 32x32 smem-tiled transpose
__global__ __launch_bounds__(256) void v_transpose_split_kernel(const float* __restrict__ v)
{
    __shared__ float T[32][33];
    const int tid = threadIdx.x;
    const int tx = tid & 31;
    const int ty = tid >> 5;          // 0..7
    const int s0 = blockIdx.x * 32;
    const int d0 = blockIdx.y * 32;
    const int bh = blockIdx.z;
    const int b  = bh >> 4;
    const int h  = bh & 15;

    #pragma unroll
    for (int i = 0; i < 4; i++) {
        int r = ty + i * 8;
        T[r][tx] = v[((size_t)(b * SEQ + s0 + r)) * D_MODEL + h * DK + d0 + tx];
    }
    __syncthreads();
    #pragma unroll
    for (int i = 0; i < 4; i++) {
        int dr = ty + i * 8;
        float x = T[tx][dr];
        __nv_bfloat16 hv = __float2bfloat16_rn(x);
        __nv_bfloat16 lv = __float2bfloat16_rn(x - __bfloat162float(hv));
        size_t off = ((size_t)(bh * DK + d0 + dr)) * SEQ + s0 + tx;
        g_vth[off] = hv;
        g_vtl[off] = lv;
    }
}

// ---------------------------------------------------------------------------
// Flash attention v5 — tensor cores, precomputed splits, cp.async staging.
// 128 threads = 4 warps; BR=64 queries (m16/warp), BC=64 keys.
// 2 blocks/SM co-resident (independent sync domains) for latency hiding.
// ---------------------------------------------------------------------------
#define FP 72   // bf16 pitch (144B rows -> conflict-free b-frag LDS, 16B aligned)

__device__ __forceinline__ void mma16816(float* c,
    unsigned a0, unsigned a1, unsigned a2, unsigned a3,
    unsigned b0, unsigned b1)
{
    asm volatile(
        "mma.sync.aligned.m16n8k16.row.col.f32.bf16.bf16.f32 "
        "{%0,%1,%2,%3},{%4,%5,%6,%7},{%8,%9},{%0,%1,%2,%3};\n"
        : "+f"(c[0]), "+f"(c[1]), "+f"(c[2]), "+f"(c[3])
        : "r"(a0), "r"(a1), "r"(a2), "r"(a3), "r"(b0), "r"(b1));
}

__device__ __forceinline__ void cpasync16(void* smem_dst, const void* gsrc)
{
    unsigned s = (unsigned)__cvta_generic_to_shared(smem_dst);
    asm volatile("cp.async.cg.shared.global [%0], [%1], 16;\n" :: "r"(s), "l"(gsrc));
}

__global__ __launch_bounds__(128) void flash_mma_kernel(float* __restrict__ o)
{
    __shared__ __align__(16) __nv_bfloat16 Khs[64 * FP];
    __shared__ __align__(16) __nv_bfloat16 Kls[64 * FP];
    __shared__ __align__(16) __nv_bfloat16 Vhs[64 * FP];
    __shared__ __align__(16) __nv_bfloat16 Vls[64 * FP];

    const int bh = blockIdx.y;
    const int b  = bh >> 4;
    const int h  = bh & 15;
    const int qt = (int)gridDim.x - 1 - (int)blockIdx.x;   // long blocks first
    const int q0 = qt * 64;
    const int tid  = threadIdx.x;
    const int warp = tid >> 5;        // 0..3
    const int lane = tid & 31;
    const int g    = lane >> 2;       // 0..7
    const int tig  = lane & 3;        // 0..3
    const int wr0  = q0 + warp * 16;  // this warp's first query row

    // ---- load Q A-fragments (precomputed hi/lo bf16, already scaled) ----
    unsigned qh[4][4], ql[4][4];
    {
        const size_t r0 = ((size_t)(b * SEQ + wr0 + g)) * D_MODEL + h * DK;
        const size_t r1 = r0 + (size_t)8 * D_MODEL;
        #pragma unroll
        for (int kt = 0; kt < 4; kt++) {
            int d0 = kt * 16 + 2 * tig;
            qh[kt][0] = *(const unsigned*)&g_qh[r0 + d0];
            qh[kt][1] = *(const unsigned*)&g_qh[r1 + d0];
            qh[kt][2] = *(const unsigned*)&g_qh[r0 + d0 + 8];
            qh[kt][3] = *(const unsigned*)&g_qh[r1 + d0 + 8];
            ql[kt][0] = *(const unsigned*)&g_ql[r0 + d0];
            ql[kt][1] = *(const unsigned*)&g_ql[r1 + d0];
            ql[kt][2] = *(const unsigned*)&g_ql[r0 + d0 + 8];
            ql[kt][3] = *(const unsigned*)&g_ql[r1 + d0 + 8];
        }
    }

    float oa[8][4];
    #pragma unroll
    for (int nj = 0; nj < 8; nj++)
        #pragma unroll
        for (int e = 0; e < 4; e++) oa[nj][e] = 0.f;
    float m0 = -1e30f, m1 = -1e30f, l0 = 0.f, l1 = 0.f;

    const int kend = q0 + 64;          // causal tile skip
    for (int k0 = 0; k0 < kend; k0 += 64) {
        // ---- stage K rows + V^T rows via cp.async (pure copies) ----
        __syncthreads();               // prior tile's readers done
        {
            const __nv_bfloat16* kbase  = g_kh;
            const __nv_bfloat16* klbase = g_kl;
            #pragma unroll
            for (int it = 0; it < 4; it++) {
                int c  = tid + it * 128;        // 0..511
                int r  = c >> 3;                // row 0..63
                int ch = c & 7;                 // 16B chunk
                size_t ksrc = ((size_t)(b * SEQ + k0 + r)) * D_MODEL + h * DK + ch * 8;
                cpasync16(&Khs[r * FP + ch * 8], kbase  + ksrc);
                cpasync16(&Kls[r * FP + ch * 8], klbase + ksrc);
                size_t vsrc = ((size_t)(bh * DK + r)) * SEQ + k0 + ch * 8;
                cpasync16(&Vhs[r * FP + ch * 8], g_vth + vsrc);
                cpasync16(&Vls[r * FP + ch * 8], g_vtl + vsrc);
            }
        }
        asm volatile("cp.async.commit_group;\n" ::: "memory");
        asm volatile("cp.async.wait_group 0;\n" ::: "memory");
        __syncthreads();

        // ---- S = Q.K^T : 8 n-tiles x 4 k-tiles x 3 terms ----
        float s[8][4];
        #pragma unroll
        for (int nj = 0; nj < 8; nj++) {
            s[nj][0] = s[nj][1] = s[nj][2] = s[nj][3] = 0.f;
            const int krow = (nj * 8 + g) * FP;
            #pragma unroll
            for (int kt = 0; kt < 4; kt++) {
                int off = krow + kt * 16 + 2 * tig;
                unsigned bh0 = *(const unsigned*)&Khs[off];
                unsigned bh1 = *(const unsigned*)&Khs[off + 8];
                unsigned bl0 = *(const unsigned*)&Kls[off];
                unsigned bl1 = *(const unsigned*)&Kls[off + 8];
                mma16816(s[nj], qh[kt][0], qh[kt][1], qh[kt][2], qh[kt][3], bh0, bh1);
                mma16816(s[nj], ql[kt][0], ql[kt][1], ql[kt][2], ql[kt][3], bh0, bh1);
                mma16816(s[nj], qh[kt][0], qh[kt][1], qh[kt][2], qh[kt][3], bl0, bl1);
            }
        }

        // ---- causal mask (only near the diagonal for this warp) ----
        if (k0 + 63 > wr0 + g) {
            int r0 = wr0 + g, r1 = r0 + 8;
            #pragma unroll
            for (int nj = 0; nj < 8; nj++) {
                int c = k0 + nj * 8 + 2 * tig;
                if (c     > r0) s[nj][0] = -1e30f;
                if (c + 1 > r0) s[nj][1] = -1e30f;
                if (c     > r1) s[nj][2] = -1e30f;
                if (c + 1 > r1) s[nj][3] = -1e30f;
            }
        }

        // ---- online softmax (rows g and g+8; reduce over tig lanes) ----
        float rm0 = -1e30f, rm1 = -1e30f;
        #pragma unroll
        for (int nj = 0; nj < 8; nj++) {
            rm0 = fmaxf(rm0, fmaxf(s[nj][0], s[nj][1]));
            rm1 = fmaxf(rm1, fmaxf(s[nj][2], s[nj][3]));
        }
        rm0 = fmaxf(rm0, __shfl_xor_sync(0xffffffffu, rm0, 1));
        rm0 = fmaxf(rm0, __shfl_xor_sync(0xffffffffu, rm0, 2));
        rm1 = fmaxf(rm1, __shfl_xor_sync(0xffffffffu, rm1, 1));
        rm1 = fmaxf(rm1, __shfl_xor_sync(0xffffffffu, rm1, 2));

        float mn0 = fmaxf(m0, rm0), mn1 = fmaxf(m1, rm1);
        float corr0 = __expf(m0 - mn0), corr1 = __expf(m1 - mn1);
        float rs0 = 0.f, rs1 = 0.f;
        #pragma unroll
        for (int nj = 0; nj < 8; nj++) {
            s[nj][0] = __expf(s[nj][0] - mn0);
            s[nj][1] = __expf(s[nj][1] - mn0);
            s[nj][2] = __expf(s[nj][2] - mn1);
            s[nj][3] = __expf(s[nj][3] - mn1);
            rs0 += s[nj][0] + s[nj][1];
            rs1 += s[nj][2] + s[nj][3];
        }
        rs0 += __shfl_xor_sync(0xffffffffu, rs0, 1);
        rs0 += __shfl_xor_sync(0xffffffffu, rs0, 2);
        rs1 += __shfl_xor_sync(0xffffffffu, rs1, 1);
        rs1 += __shfl_xor_sync(0xffffffffu, rs1, 2);
        l0 = l0 * corr0 + rs0;
        l1 = l1 * corr1 + rs1;
        m0 = mn0; m1 = mn1;

        #pragma unroll
        for (int nj = 0; nj < 8; nj++) {
            oa[nj][0] *= corr0; oa[nj][1] *= corr0;
            oa[nj][2] *= corr1; oa[nj][3] *= corr1;
        }

        // ---- convert P to A-fragments (hi/lo): QK C-frags ARE PV A-frags ----
        unsigned pah[4][4], pal[4][4];
        #pragma unroll
        for (int kt = 0; kt < 4; kt++) {
            split2(s[2*kt][0],   s[2*kt][1],   pah[kt][0], pal[kt][0]);
            split2(s[2*kt][2],   s[2*kt][3],   pah[kt][1], pal[kt][1]);
            split2(s[2*kt+1][0], s[2*kt+1][1], pah[kt][2], pal[kt][2]);
            split2(s[2*kt+1][2], s[2*kt+1][3], pah[kt][3], pal[kt][3]);
        }

        // ---- O += P.V : 8 n-tiles (dims) x 4 k-tiles (keys) x 3 terms ----
        #pragma unroll
        for (int nj = 0; nj < 8; nj++) {
            const int vrow = (nj * 8 + g) * FP;
            #pragma unroll
            for (int kt = 0; kt < 4; kt++) {
                int off = vrow + kt * 16 + 2 * tig;
                unsigned bh0 = *(const unsigned*)&Vhs[off];
                unsigned bh1 = *(const unsigned*)&Vhs[off + 8];
                unsigned bl0 = *(const unsigned*)&Vls[off];
                unsigned bl1 = *(const unsigned*)&Vls[off + 8];
                mma16816(oa[nj], pah[kt][0], pah[kt][1], pah[kt][2], pah[kt][3], bh0, bh1);
                mma16816(oa[nj], pal[kt][0], pal[kt][1], pal[kt][2], pal[kt][3], bh0, bh1);
                mma16816(oa[nj], pah[kt][0], pah[kt][1], pah[kt][2], pah[kt][3], bl0, bl1);
            }
        }
    }

    // ---- write O ----
    {
        float inv0 = 1.0f / l0, inv1 = 1.0f / l1;
        float* or0 = o + ((size_t)(b * SEQ + wr0 + g)) * D_MODEL + h * DK;
        float* or1 = or0 + (size_t)8 * D_MODEL;
        #pragma unroll
        for (int nj = 0; nj < 8; nj++) {
            int d = nj * 8 + 2 * tig;
            *(float2*)(or0 + d) = make_float2(oa[nj][0] * inv0, oa[nj][1] * inv0);
            *(float2*)(or1 + d) = make_float2(oa[nj][2] * inv1, oa[nj][3] * inv1);
        }
    }
}

// ---------------------------------------------------------------------------
// Launch
// ---------------------------------------------------------------------------
extern "C" void kernel_launch(void* const* d_in, const int* in_sizes, int n_in,
                              void* d_out, int out_size)
{
    const float* x  = (const float*)d_in[0];
    const float* Wq = (const float*)d_in[1];
    const float* Wk = (const float*)d_in[2];
    const float* Wv = (const float*)d_in[3];
    const float* Wo = (const float*)d_in[4];
    const int*   tp = (const int*)d_in[5];
    float* out = (float*)d_out;

    float *qp, *kp, *vp, *op;
    cudaGetSymbolAddress((void**)&qp, g_q);
    cudaGetSymbolAddress((void**)&kp, g_k);
    cudaGetSymbolAddress((void**)&vp, g_v);
    cudaGetSymbolAddress((void**)&op, g_o);

    // 1) QKV projections
    dim3 g1(D_MODEL / BN, M_TOT / BM, 3);
    sgemm_abT<<<g1, 256>>>(x, Wq, Wk, Wv, qp, kp, vp, M_TOT, D_MODEL, D_MODEL);

    // 2) RoPE on Q and K
    int npairs_r = BATCH * SEQ * NHEAD * (DK / 2);
    rope_kernel<<<(npairs_r + 255) / 256, 256>>>(qp, kp, tp);

    // 3) Precompute bf16 hi/lo splits (Q scaled; V transposed per head)
    qk_split_kernel<<<(NPAIRS + 255) / 256, 256>>>(qp, kp);
    v_transpose_split_kernel<<<dim3(SEQ / 32, DK / 32, BATCH * NHEAD), 256>>>(vp);

    // 4) Causal flash attention (tensor cores, async staging)
    flash_mma_kernel<<<dim3(SEQ / 64, BATCH * NHEAD), 128>>>(op);

    // 5) Output projection
    dim3 g2(D_MODEL / BN, M_TOT / BM, 1);
    sgemm_abT<<<g2, 256>>>(op, Wo, Wo, Wo, out, out, out, M_TOT, D_MODEL, D_MODEL);
}

// round 9
// speedup vs baseline: 1.6893x; 1.0191x over previous
#include <cuda_runtime.h>
#include <cuda_bf16.h>

#define D_MODEL 1024
#define NHEAD   16
#define DK      64
#define BATCH   2
#define SEQ     2048
#define M_TOT   (BATCH*SEQ)   // 4096
#define NPAIRS  (M_TOT*D_MODEL/2)

// Scratch (allocation-free rule: __device__ globals)
__device__ float g_q[(size_t)BATCH*SEQ*D_MODEL];
__device__ float g_k[(size_t)BATCH*SEQ*D_MODEL];
__device__ float g_v[(size_t)BATCH*SEQ*D_MODEL];
__device__ float g_o[(size_t)BATCH*SEQ*D_MODEL];
// precomputed bf16 hi/lo splits
__device__ __nv_bfloat16 g_qh[(size_t)M_TOT*D_MODEL];
__device__ __nv_bfloat16 g_ql[(size_t)M_TOT*D_MODEL];
__device__ __nv_bfloat16 g_kh[(size_t)M_TOT*D_MODEL];
__device__ __nv_bfloat16 g_kl[(size_t)M_TOT*D_MODEL];
// V transposed per (b,h): [bh][dim][seq]
__device__ __nv_bfloat16 g_vth[(size_t)M_TOT*D_MODEL];
__device__ __nv_bfloat16 g_vtl[(size_t)M_TOT*D_MODEL];

// ---------------------------------------------------------------------------
// SGEMM: C[M,N] = A[M,K] * B[N,K]^T  (measured 62 TF/s ~ 82% fp32 peak; keep)
// ---------------------------------------------------------------------------
#define BM 64
#define BN 64
#define BK 16

__global__ __launch_bounds__(256) void sgemm_abT(
    const float* __restrict__ A,
    const float* __restrict__ B0, const float* __restrict__ B1, const float* __restrict__ B2,
    float* __restrict__ C0, float* __restrict__ C1, float* __restrict__ C2,
    int M, int N, int K)
{
    const float* B; float* C;
    if (blockIdx.z == 0)      { B = B0; C = C0; }
    else if (blockIdx.z == 1) { B = B1; C = C1; }
    else                      { B = B2; C = C2; }

    __shared__ float As[BK][BM + 1];
    __shared__ float Bs[BK][BN + 1];

    const int tid = threadIdx.x;
    const int tx = tid & 15;
    const int ty = tid >> 4;
    const int row0 = blockIdx.y * BM;
    const int col0 = blockIdx.x * BN;

    float acc[4][4] = {};

    for (int k0 = 0; k0 < K; k0 += BK) {
        #pragma unroll
        for (int i = 0; i < 4; i++) {
            int idx = tid + i * 256;
            int r  = idx >> 4;
            int kk = idx & 15;
            As[kk][r] = A[(size_t)(row0 + r) * K + k0 + kk];
            Bs[kk][r] = B[(size_t)(col0 + r) * K + k0 + kk];
        }
        __syncthreads();

        #pragma unroll
        for (int kk = 0; kk < BK; kk++) {
            float a[4], b[4];
            #pragma unroll
            for (int i = 0; i < 4; i++) a[i] = As[kk][ty * 4 + i];
            #pragma unroll
            for (int j = 0; j < 4; j++) b[j] = Bs[kk][tx * 4 + j];
            #pragma unroll
            for (int i = 0; i < 4; i++)
                #pragma unroll
                for (int j = 0; j < 4; j++)
                    acc[i][j] += a[i] * b[j];
        }
        __syncthreads();
    }

    #pragma unroll
    for (int i = 0; i < 4; i++)
        #pragma unroll
        for (int j = 0; j < 4; j++)
            C[(size_t)(row0 + ty * 4 + i) * N + col0 + tx * 4 + j] = acc[i][j];
}

// ---------------------------------------------------------------------------
// RoPE in-place on Q and K (unchanged)
// ---------------------------------------------------------------------------
__global__ void rope_kernel(float* __restrict__ q, float* __restrict__ k,
                            const int* __restrict__ pos)
{
    int idx = blockIdx.x * blockDim.x + threadIdx.x;
    if (idx >= BATCH * SEQ * NHEAD * (DK / 2)) return;
    int i  = idx & 31;
    int h  = (idx >> 5) & 15;
    int bs = idx >> 9;
    int p  = pos[bs];

    float inv = __expf(-(float)(2 * i) * (9.210340371976184f / 64.0f));
    float ang = (float)p * inv;
    float sn, cs;
    sincosf(ang, &sn, &cs);

    size_t off = (size_t)bs * D_MODEL + h * DK + 2 * i;
    float e = q[off], o = q[off + 1];
    q[off]     = e * cs - o * sn;
    q[off + 1] = e * sn + o * cs;
    e = k[off]; o = k[off + 1];
    k[off]     = e * cs - o * sn;
    k[off + 1] = e * sn + o * cs;
}

// ---------------------------------------------------------------------------
// bf16 hi/lo split helpers
// ---------------------------------------------------------------------------
__device__ __forceinline__ void split2(float x, float y, unsigned& h, unsigned& l)
{
    __nv_bfloat162 hh = __floats2bfloat162_rn(x, y);
    float rx = x - __bfloat162float(hh.x);
    float ry = y - __bfloat162float(hh.y);
    __nv_bfloat162 ll = __floats2bfloat162_rn(rx, ry);
    h = *reinterpret_cast<unsigned*>(&hh);
    l = *reinterpret_cast<unsigned*>(&ll);
}

// Q (scaled by 1/8) and K -> hi/lo bf16 pairs, same layout as source
__global__ void qk_split_kernel(const float* __restrict__ q, const float* __restrict__ k)
{
    int idx = blockIdx.x * blockDim.x + threadIdx.x;
    if (idx >= NPAIRS) return;
    unsigned* qh = reinterpret_cast<unsigned*>(g_qh);
    unsigned* ql = reinterpret_cast<unsigned*>(g_ql);
    unsigned* kh = reinterpret_cast<unsigned*>(g_kh);
    unsigned* kl = reinterpret_cast<unsigned*>(g_kl);
    float2 xq = ((const float2*)q)[idx];
    unsigned h, l;
    split2(xq.x * 0.125f, xq.y * 0.125f, h, l);
    qh[idx] = h; ql[idx] = l;
    float2 xk = ((const float2*)k)[idx];
    split2(xk.x, xk.y, h, l);
    kh[idx] = h; kl[idx] = l;
}

// V -> transposed per-(b,h) hi/lo bf16: vt[bh][d][s]; 32x32 smem-tiled transpose
__global__ __launch_bounds__(256) void v_transpose_split_kernel(const float* __restrict__ v)
{
    __shared__ float T[32][33];
    const int tid = threadIdx.x;
    const int tx = tid & 31;
    const int ty = tid >> 5;          // 0..7
    const int s0 = blockIdx.x * 32;
    const int d0 = blockIdx.y * 32;
    const int bh = blockIdx.z;
    const int b  = bh >> 4;
    const int h  = bh & 15;

    #pragma unroll
    for (int i = 0; i < 4; i++) {
        int r = ty + i * 8;
        T[r][tx] = v[((size_t)(b * SEQ + s0 + r)) * D_MODEL + h * DK + d0 + tx];
    }
    __syncthreads();
    #pragma unroll
    for (int i = 0; i < 4; i++) {
        int dr = ty + i * 8;
        float x = T[tx][dr];
        __nv_bfloat16 hv = __float2bfloat16_rn(x);
        __nv_bfloat16 lv = __float2bfloat16_rn(x - __bfloat162float(hv));
        size_t off = ((size_t)(bh * DK + d0 + dr)) * SEQ + s0 + tx;
        g_vth[off] = hv;
        g_vtl[off] = lv;
    }
}

// ---------------------------------------------------------------------------
// Flash attention v6 — tensor cores; MMA loops reordered so consecutive
// HMMAs target DIFFERENT accumulators (dep distance 8 instead of 1).
// 128 threads = 4 warps; BR=64 queries (m16/warp), BC=64 keys; 2 blocks/SM.
// ---------------------------------------------------------------------------
#define FP 72   // bf16 pitch (144B rows -> conflict-free b-frag LDS, 16B aligned)

__device__ __forceinline__ void mma16816(float* c,
    unsigned a0, unsigned a1, unsigned a2, unsigned a3,
    unsigned b0, unsigned b1)
{
    asm volatile(
        "mma.sync.aligned.m16n8k16.row.col.f32.bf16.bf16.f32 "
        "{%0,%1,%2,%3},{%4,%5,%6,%7},{%8,%9},{%0,%1,%2,%3};\n"
        : "+f"(c[0]), "+f"(c[1]), "+f"(c[2]), "+f"(c[3])
        : "r"(a0), "r"(a1), "r"(a2), "r"(a3), "r"(b0), "r"(b1));
}

__device__ __forceinline__ void cpasync16(void* smem_dst, const void* gsrc)
{
    unsigned s = (unsigned)__cvta_generic_to_shared(smem_dst);
    asm volatile("cp.async.cg.shared.global [%0], [%1], 16;\n" :: "r"(s), "l"(gsrc));
}

__global__ __launch_bounds__(128) void flash_mma_kernel(float* __restrict__ o)
{
    __shared__ __align__(16) __nv_bfloat16 Khs[64 * FP];
    __shared__ __align__(16) __nv_bfloat16 Kls[64 * FP];
    __shared__ __align__(16) __nv_bfloat16 Vhs[64 * FP];
    __shared__ __align__(16) __nv_bfloat16 Vls[64 * FP];

    const int bh = blockIdx.y;
    const int b  = bh >> 4;
    const int h  = bh & 15;
    const int qt = (int)gridDim.x - 1 - (int)blockIdx.x;   // long blocks first
    const int q0 = qt * 64;
    const int tid  = threadIdx.x;
    const int warp = tid >> 5;        // 0..3
    const int lane = tid & 31;
    const int g    = lane >> 2;       // 0..7
    const int tig  = lane & 3;        // 0..3
    const int wr0  = q0 + warp * 16;  // this warp's first query row

    // ---- load Q A-fragments (precomputed hi/lo bf16, already scaled) ----
    unsigned qh[4][4], ql[4][4];
    {
        const size_t r0 = ((size_t)(b * SEQ + wr0 + g)) * D_MODEL + h * DK;
        const size_t r1 = r0 + (size_t)8 * D_MODEL;
        #pragma unroll
        for (int kt = 0; kt < 4; kt++) {
            int d0 = kt * 16 + 2 * tig;
            qh[kt][0] = *(const unsigned*)&g_qh[r0 + d0];
            qh[kt][1] = *(const unsigned*)&g_qh[r1 + d0];
            qh[kt][2] = *(const unsigned*)&g_qh[r0 + d0 + 8];
            qh[kt][3] = *(const unsigned*)&g_qh[r1 + d0 + 8];
            ql[kt][0] = *(const unsigned*)&g_ql[r0 + d0];
            ql[kt][1] = *(const unsigned*)&g_ql[r1 + d0];
            ql[kt][2] = *(const unsigned*)&g_ql[r0 + d0 + 8];
            ql[kt][3] = *(const unsigned*)&g_ql[r1 + d0 + 8];
        }
    }

    float oa[8][4];
    #pragma unroll
    for (int nj = 0; nj < 8; nj++)
        #pragma unroll
        for (int e = 0; e < 4; e++) oa[nj][e] = 0.f;
    float m0 = -1e30f, m1 = -1e30f, l0 = 0.f, l1 = 0.f;

    const int kend = q0 + 64;          // causal tile skip
    for (int k0 = 0; k0 < kend; k0 += 64) {
        // ---- stage K rows + V^T rows via cp.async (pure copies) ----
        __syncthreads();               // prior tile's readers done
        {
            #pragma unroll
            for (int it = 0; it < 4; it++) {
                int c  = tid + it * 128;        // 0..511
                int r  = c >> 3;                // row 0..63
                int ch = c & 7;                 // 16B chunk
                size_t ksrc = ((size_t)(b * SEQ + k0 + r)) * D_MODEL + h * DK + ch * 8;
                cpasync16(&Khs[r * FP + ch * 8], g_kh + ksrc);
                cpasync16(&Kls[r * FP + ch * 8], g_kl + ksrc);
                size_t vsrc = ((size_t)(bh * DK + r)) * SEQ + k0 + ch * 8;
                cpasync16(&Vhs[r * FP + ch * 8], g_vth + vsrc);
                cpasync16(&Vls[r * FP + ch * 8], g_vtl + vsrc);
            }
        }
        asm volatile("cp.async.commit_group;\n" ::: "memory");
        asm volatile("cp.async.wait_group 0;\n" ::: "memory");
        __syncthreads();

        // ---- S = Q.K^T : kt OUTER, nj inner -> dep distance 8 ----
        float s[8][4];
        #pragma unroll
        for (int nj = 0; nj < 8; nj++) {
            s[nj][0] = s[nj][1] = s[nj][2] = s[nj][3] = 0.f;
        }
        #pragma unroll
        for (int kt = 0; kt < 4; kt++) {
            unsigned kb0[8], kb1[8], kc0[8], kc1[8];
            #pragma unroll
            for (int nj = 0; nj < 8; nj++) {
                int off = (nj * 8 + g) * FP + kt * 16 + 2 * tig;
                kb0[nj] = *(const unsigned*)&Khs[off];
                kb1[nj] = *(const unsigned*)&Khs[off + 8];
                kc0[nj] = *(const unsigned*)&Kls[off];
                kc1[nj] = *(const unsigned*)&Kls[off + 8];
            }
            #pragma unroll
            for (int nj = 0; nj < 8; nj++)
                mma16816(s[nj], qh[kt][0], qh[kt][1], qh[kt][2], qh[kt][3], kb0[nj], kb1[nj]);
            #pragma unroll
            for (int nj = 0; nj < 8; nj++)
                mma16816(s[nj], ql[kt][0], ql[kt][1], ql[kt][2], ql[kt][3], kb0[nj], kb1[nj]);
            #pragma unroll
            for (int nj = 0; nj < 8; nj++)
                mma16816(s[nj], qh[kt][0], qh[kt][1], qh[kt][2], qh[kt][3], kc0[nj], kc1[nj]);
        }

        // ---- causal mask (only near the diagonal for this warp) ----
        if (k0 + 63 > wr0 + g) {
            int r0 = wr0 + g, r1 = r0 + 8;
            #pragma unroll
            for (int nj = 0; nj < 8; nj++) {
                int c = k0 + nj * 8 + 2 * tig;
                if (c     > r0) s[nj][0] = -1e30f;
                if (c + 1 > r0) s[nj][1] = -1e30f;
                if (c     > r1) s[nj][2] = -1e30f;
                if (c + 1 > r1) s[nj][3] = -1e30f;
            }
        }

        // ---- online softmax (rows g and g+8; reduce over tig lanes) ----
        float rm0 = -1e30f, rm1 = -1e30f;
        #pragma unroll
        for (int nj = 0; nj < 8; nj++) {
            rm0 = fmaxf(rm0, fmaxf(s[nj][0], s[nj][1]));
            rm1 = fmaxf(rm1, fmaxf(s[nj][2], s[nj][3]));
        }
        rm0 = fmaxf(rm0, __shfl_xor_sync(0xffffffffu, rm0, 1));
        rm0 = fmaxf(rm0, __shfl_xor_sync(0xffffffffu, rm0, 2));
        rm1 = fmaxf(rm1, __shfl_xor_sync(0xffffffffu, rm1, 1));
        rm1 = fmaxf(rm1, __shfl_xor_sync(0xffffffffu, rm1, 2));

        float mn0 = fmaxf(m0, rm0), mn1 = fmaxf(m1, rm1);
        float corr0 = __expf(m0 - mn0), corr1 = __expf(m1 - mn1);
        float rs0 = 0.f, rs1 = 0.f;
        #pragma unroll
        for (int nj = 0; nj < 8; nj++) {
            s[nj][0] = __expf(s[nj][0] - mn0);
            s[nj][1] = __expf(s[nj][1] - mn0);
            s[nj][2] = __expf(s[nj][2] - mn1);
            s[nj][3] = __expf(s[nj][3] - mn1);
            rs0 += s[nj][0] + s[nj][1];
            rs1 += s[nj][2] + s[nj][3];
        }
        rs0 += __shfl_xor_sync(0xffffffffu, rs0, 1);
        rs0 += __shfl_xor_sync(0xffffffffu, rs0, 2);
        rs1 += __shfl_xor_sync(0xffffffffu, rs1, 1);
        rs1 += __shfl_xor_sync(0xffffffffu, rs1, 2);
        l0 = l0 * corr0 + rs0;
        l1 = l1 * corr1 + rs1;
        m0 = mn0; m1 = mn1;

        #pragma unroll
        for (int nj = 0; nj < 8; nj++) {
            oa[nj][0] *= corr0; oa[nj][1] *= corr0;
            oa[nj][2] *= corr1; oa[nj][3] *= corr1;
        }

        // ---- convert P to A-fragments (hi/lo): QK C-frags ARE PV A-frags ----
        unsigned pah[4][4], pal[4][4];
        #pragma unroll
        for (int kt = 0; kt < 4; kt++) {
            split2(s[2*kt][0],   s[2*kt][1],   pah[kt][0], pal[kt][0]);
            split2(s[2*kt][2],   s[2*kt][3],   pah[kt][1], pal[kt][1]);
            split2(s[2*kt+1][0], s[2*kt+1][1], pah[kt][2], pal[kt][2]);
            split2(s[2*kt+1][2], s[2*kt+1][3], pah[kt][3], pal[kt][3]);
        }

        // ---- O += P.V : kt OUTER, nj inner -> dep distance 8 ----
        #pragma unroll
        for (int kt = 0; kt < 4; kt++) {
            unsigned vb0[8], vb1[8], vc0[8], vc1[8];
            #pragma unroll
            for (int nj = 0; nj < 8; nj++) {
                int off = (nj * 8 + g) * FP + kt * 16 + 2 * tig;
                vb0[nj] = *(const unsigned*)&Vhs[off];
                vb1[nj] = *(const unsigned*)&Vhs[off + 8];
                vc0[nj] = *(const unsigned*)&Vls[off];
                vc1[nj] = *(const unsigned*)&Vls[off + 8];
            }
            #pragma unroll
            for (int nj = 0; nj < 8; nj++)
                mma16816(oa[nj], pah[kt][0], pah[kt][1], pah[kt][2], pah[kt][3], vb0[nj], vb1[nj]);
            #pragma unroll
            for (int nj = 0; nj < 8; nj++)
                mma16816(oa[nj], pal[kt][0], pal[kt][1], pal[kt][2], pal[kt][3], vb0[nj], vb1[nj]);
            #pragma unroll
            for (int nj = 0; nj < 8; nj++)
                mma16816(oa[nj], pah[kt][0], pah[kt][1], pah[kt][2], pah[kt][3], vc0[nj], vc1[nj]);
        }
    }

    // ---- write O ----
    {
        float inv0 = 1.0f / l0, inv1 = 1.0f / l1;
        float* or0 = o + ((size_t)(b * SEQ + wr0 + g)) * D_MODEL + h * DK;
        float* or1 = or0 + (size_t)8 * D_MODEL;
        #pragma unroll
        for (int nj = 0; nj < 8; nj++) {
            int d = nj * 8 + 2 * tig;
            *(float2*)(or0 + d) = make_float2(oa[nj][0] * inv0, oa[nj][1] * inv0);
            *(float2*)(or1 + d) = make_float2(oa[nj][2] * inv1, oa[nj][3] * inv1);
        }
    }
}

// ---------------------------------------------------------------------------
// Launch
// ---------------------------------------------------------------------------
extern "C" void kernel_launch(void* const* d_in, const int* in_sizes, int n_in,
                              void* d_out, int out_size)
{
    const float* x  = (const float*)d_in[0];
    const float* Wq = (const float*)d_in[1];
    const float* Wk = (const float*)d_in[2];
    const float* Wv = (const float*)d_in[3];
    const float* Wo = (const float*)d_in[4];
    const int*   tp = (const int*)d_in[5];
    float* out = (float*)d_out;

    float *qp, *kp, *vp, *op;
    cudaGetSymbolAddress((void**)&qp, g_q);
    cudaGetSymbolAddress((void**)&kp, g_k);
    cudaGetSymbolAddress((void**)&vp, g_v);
    cudaGetSymbolAddress((void**)&op, g_o);

    // 1) QKV projections
    dim3 g1(D_MODEL / BN, M_TOT / BM, 3);
    sgemm_abT<<<g1, 256>>>(x, Wq, Wk, Wv, qp, kp, vp, M_TOT, D_MODEL, D_MODEL);

    // 2) RoPE on Q and K
    int npairs_r = BATCH * SEQ * NHEAD * (DK / 2);
    rope_kernel<<<(npairs_r + 255) / 256, 256>>>(qp, kp, tp);

    // 3) Precompute bf16 hi/lo splits (Q scaled; V transposed per head)
    qk_split_kernel<<<(NPAIRS + 255) / 256, 256>>>(qp, kp);
    v_transpose_split_kernel<<<dim3(SEQ / 32, DK / 32, BATCH * NHEAD), 256>>>(vp);

    // 4) Causal flash attention (tensor cores, ILP-ordered MMAs)
    flash_mma_kernel<<<dim3(SEQ / 64, BATCH * NHEAD), 128>>>(op);

    // 5) Output projection
    dim3 g2(D_MODEL / BN, M_TOT / BM, 1);
    sgemm_abT<<<g2, 256>>>(op, Wo, Wo, Wo, out, out, out, M_TOT, D_MODEL, D_MODEL);
}

// round 12
// speedup vs baseline: 4.9069x; 2.9048x over previous
#include <cuda_runtime.h>
#include <cuda_bf16.h>
#include <cstdint>

#define D_MODEL 1024
#define NHEAD   16
#define DK      64
#define BATCH   2
#define SEQ     2048
#define M_TOT   (BATCH*SEQ)   // 4096
#define NPAIRS  (M_TOT*D_MODEL/2)
#define WPAIRS  (D_MODEL*D_MODEL/2)

// Scratch (allocation-free rule: __device__ globals)
__device__ float g_q[(size_t)M_TOT*D_MODEL];
__device__ float g_k[(size_t)M_TOT*D_MODEL];
__device__ float g_v[(size_t)M_TOT*D_MODEL];
__device__ float g_o[(size_t)M_TOT*D_MODEL];
// bf16 hi/lo splits
__device__ __nv_bfloat16 g_xh[(size_t)M_TOT*D_MODEL];
__device__ __nv_bfloat16 g_xl[(size_t)M_TOT*D_MODEL];
__device__ __nv_bfloat16 g_wh[(size_t)4*D_MODEL*D_MODEL];
__device__ __nv_bfloat16 g_wl[(size_t)4*D_MODEL*D_MODEL];
__device__ __nv_bfloat16 g_oh[(size_t)M_TOT*D_MODEL];
__device__ __nv_bfloat16 g_ol[(size_t)M_TOT*D_MODEL];
__device__ __nv_bfloat16 g_qh[(size_t)M_TOT*D_MODEL];
__device__ __nv_bfloat16 g_ql[(size_t)M_TOT*D_MODEL];
__device__ __nv_bfloat16 g_kh[(size_t)M_TOT*D_MODEL];
__device__ __nv_bfloat16 g_kl[(size_t)M_TOT*D_MODEL];
__device__ __nv_bfloat16 g_vth[(size_t)M_TOT*D_MODEL];   // V^T per (b,h): [bh][dim][seq]
__device__ __nv_bfloat16 g_vtl[(size_t)M_TOT*D_MODEL];

// ---------------------------------------------------------------------------
// common helpers
// ---------------------------------------------------------------------------
__device__ __forceinline__ void split2(float x, float y, unsigned& h, unsigned& l)
{
    __nv_bfloat162 hh = __floats2bfloat162_rn(x, y);
    float rx = x - __bfloat162float(hh.x);
    float ry = y - __bfloat162float(hh.y);
    __nv_bfloat162 ll = __floats2bfloat162_rn(rx, ry);
    h = *reinterpret_cast<unsigned*>(&hh);
    l = *reinterpret_cast<unsigned*>(&ll);
}

__device__ __forceinline__ void mma16816(float* c,
    unsigned a0, unsigned a1, unsigned a2, unsigned a3,
    unsigned b0, unsigned b1)
{
    asm volatile(
        "mma.sync.aligned.m16n8k16.row.col.f32.bf16.bf16.f32 "
        "{%0,%1,%2,%3},{%4,%5,%6,%7},{%8,%9},{%0,%1,%2,%3};\n"
        : "+f"(c[0]), "+f"(c[1]), "+f"(c[2]), "+f"(c[3])
        : "r"(a0), "r"(a1), "r"(a2), "r"(a3), "r"(b0), "r"(b1));
}

__device__ __forceinline__ uint32_t smem_u32(const void* p) {
    uint32_t a;
    asm("{ .reg .u64 t; cvta.to.shared.u64 t, %1; cvt.u32.u64 %0, t; }"
        : "=r"(a) : "l"(p));
    return a;
}
__device__ __forceinline__ void cp16r(uint32_t saddr, const void* gsrc)
{
    asm volatile("cp.async.cg.shared.global [%0], [%1], 16;\n" :: "r"(saddr), "l"(gsrc));
}
__device__ __forceinline__ void cpasync16(void* smem_dst, const void* gsrc)
{
    unsigned s = (unsigned)__cvta_generic_to_shared(smem_dst);
    asm volatile("cp.async.cg.shared.global [%0], [%1], 16;\n" :: "r"(s), "l"(gsrc));
}
#define CP_COMMIT() asm volatile("cp.async.commit_group;\n" ::: "memory")
#define CP_WAIT(n)  asm volatile("cp.async.wait_group %0;\n" :: "n"(n) : "memory")

// ---------------------------------------------------------------------------
// generic fp32 -> bf16 hi/lo split
// ---------------------------------------------------------------------------
__global__ void split_kernel(const float* __restrict__ src,
                             __nv_bfloat16* __restrict__ h,
                             __nv_bfloat16* __restrict__ l, int npairs)
{
    int idx = blockIdx.x * blockDim.x + threadIdx.x;
    if (idx >= npairs) return;
    float2 x = ((const float2*)src)[idx];
    unsigned hh, ll;
    split2(x.x, x.y, hh, ll);
    ((unsigned*)h)[idx] = hh;
    ((unsigned*)l)[idx] = ll;
}

// ---------------------------------------------------------------------------
// GEMM via mma.sync split-bf16: C[M,N] = A[M,K] * B[N,K]^T, fp32 out.
// 128x128 block tile, 256 threads = 8 warps (4x2), each warp m32 x n64.
// BK=64 chunks, double-buffered cp.async from pre-split bf16 hi/lo gmem.
// Smem: per buffer Ah|Al|Bh|Bl, each 128 rows x 72 bf16 pitch (144B).
// ---------------------------------------------------------------------------
#define GP 72
#define G_ARR  18432                      // bytes per array (128*72*2)
#define G_BUF  (4*G_ARR)                  // 73728 bytes per buffer
#define G_SMEM (2*G_BUF)                  // 147456 bytes

__global__ __launch_bounds__(256) void gemm_mma(
    const __nv_bfloat16* __restrict__ Ah, const __nv_bfloat16* __restrict__ Al,
    const __nv_bfloat16* Bh0, const __nv_bfloat16* Bl0, float* C0,
    const __nv_bfloat16* Bh1, const __nv_bfloat16* Bl1, float* C1,
    const __nv_bfloat16* Bh2, const __nv_bfloat16* Bl2, float* C2,
    int M, int N, int K)
{
    extern __shared__ __align__(16) char gsm[];
    const __nv_bfloat16 *Bh, *Bl; float* C;
    if (blockIdx.z == 0)      { Bh = Bh0; Bl = Bl0; C = C0; }
    else if (blockIdx.z == 1) { Bh = Bh1; Bl = Bl1; C = C1; }
    else                      { Bh = Bh2; Bl = Bl2; C = C2; }

    const uint32_t sb = smem_u32(gsm);
    const __nv_bfloat16* sm = (const __nv_bfloat16*)gsm;

    const int m0 = blockIdx.y * 128;
    const int n0 = blockIdx.x * 128;
    const int tid  = threadIdx.x;
    const int warp = tid >> 5;
    const int lane = tid & 31;
    const int g    = lane >> 2;
    const int tig  = lane & 3;
    const int wm   = warp >> 1;      // 0..3 -> m offset 32*wm
    const int wn   = warp & 1;       // 0..1 -> n offset 64*wn
    const int nk   = K >> 6;         // chunks of 64

    float c[2][8][4];
    #pragma unroll
    for (int m = 0; m < 2; m++)
        #pragma unroll
        for (int n = 0; n < 8; n++)
            c[m][n][0] = c[m][n][1] = c[m][n][2] = c[m][n][3] = 0.f;

    // ---- stage chunk kc into buffer bi ----
    #define G_STAGE(kc, bi) do {                                               \
        uint32_t bb = sb + (bi) * G_BUF;                                       \
        _Pragma("unroll")                                                      \
        for (int i = 0; i < 4; i++) {                                          \
            int idx = tid + i * 256;                                           \
            int r = idx >> 3, ch = idx & 7;                                    \
            uint32_t d = r * 144 + ch * 16;                                    \
            size_t as = (size_t)(m0 + r) * K + (kc) * 64 + ch * 8;             \
            cp16r(bb + d,            Ah + as);                                 \
            cp16r(bb + G_ARR + d,    Al + as);                                 \
            size_t bs = (size_t)(n0 + r) * K + (kc) * 64 + ch * 8;             \
            cp16r(bb + 2*G_ARR + d,  Bh + bs);                                 \
            cp16r(bb + 3*G_ARR + d,  Bl + bs);                                 \
        }                                                                      \
        CP_COMMIT();                                                           \
    } while (0)

    G_STAGE(0, 0);

    for (int kc = 0; kc < nk; kc++) {
        if (kc + 1 < nk) { G_STAGE(kc + 1, (kc + 1) & 1); CP_WAIT(1); }
        else             { CP_WAIT(0); }
        __syncthreads();

        const __nv_bfloat16* sAh = sm + (kc & 1) * (G_BUF / 2);
        const __nv_bfloat16* sAl = sAh + G_ARR / 2;
        const __nv_bfloat16* sBh = sAh + G_ARR;
        const __nv_bfloat16* sBl = sAh + 3 * (G_ARR / 2);

        #pragma unroll
        for (int kt = 0; kt < 4; kt++) {
            const int cb = kt * 16 + 2 * tig;
            unsigned ah[2][4], al[2][4];
            #pragma unroll
            for (int m = 0; m < 2; m++) {
                int rw = wm * 32 + m * 16;
                ah[m][0] = *(const unsigned*)&sAh[(rw + g)     * GP + cb];
                ah[m][1] = *(const unsigned*)&sAh[(rw + g + 8) * GP + cb];
                ah[m][2] = *(const unsigned*)&sAh[(rw + g)     * GP + cb + 8];
                ah[m][3] = *(const unsigned*)&sAh[(rw + g + 8) * GP + cb + 8];
                al[m][0] = *(const unsigned*)&sAl[(rw + g)     * GP + cb];
                al[m][1] = *(const unsigned*)&sAl[(rw + g + 8) * GP + cb];
                al[m][2] = *(const unsigned*)&sAl[(rw + g)     * GP + cb + 8];
                al[m][3] = *(const unsigned*)&sAl[(rw + g + 8) * GP + cb + 8];
            }
            unsigned bh0[8], bh1[8], bl0[8], bl1[8];
            #pragma unroll
            for (int n = 0; n < 8; n++) {
                int off = (wn * 64 + n * 8 + g) * GP + cb;
                bh0[n] = *(const unsigned*)&sBh[off];
                bh1[n] = *(const unsigned*)&sBh[off + 8];
                bl0[n] = *(const unsigned*)&sBl[off];
                bl1[n] = *(const unsigned*)&sBl[off + 8];
            }
            #pragma unroll
            for (int m = 0; m < 2; m++)
                #pragma unroll
                for (int n = 0; n < 8; n++)
                    mma16816(c[m][n], ah[m][0], ah[m][1], ah[m][2], ah[m][3], bh0[n], bh1[n]);
            #pragma unroll
            for (int m = 0; m < 2; m++)
                #pragma unroll
                for (int n = 0; n < 8; n++)
                    mma16816(c[m][n], al[m][0], al[m][1], al[m][2], al[m][3], bh0[n], bh1[n]);
            #pragma unroll
            for (int m = 0; m < 2; m++)
                #pragma unroll
                for (int n = 0; n < 8; n++)
                    mma16816(c[m][n], ah[m][0], ah[m][1], ah[m][2], ah[m][3], bl0[n], bl1[n]);
        }
        __syncthreads();
    }

    // ---- writeback ----
    #pragma unroll
    for (int m = 0; m < 2; m++) {
        float* cr = C + (size_t)(m0 + wm * 32 + m * 16 + g) * N + n0 + wn * 64 + 2 * tig;
        #pragma unroll
        for (int n = 0; n < 8; n++) {
            *(float2*)(cr + n * 8)          = make_float2(c[m][n][0], c[m][n][1]);
            *(float2*)(cr + 8 * N + n * 8)  = make_float2(c[m][n][2], c[m][n][3]);
        }
    }
    #undef G_STAGE
}

// ---------------------------------------------------------------------------
// RoPE in-place on Q and K
// ---------------------------------------------------------------------------
__global__ void rope_kernel(float* __restrict__ q, float* __restrict__ k,
                            const int* __restrict__ pos)
{
    int idx = blockIdx.x * blockDim.x + threadIdx.x;
    if (idx >= BATCH * SEQ * NHEAD * (DK / 2)) return;
    int i  = idx & 31;
    int h  = (idx >> 5) & 15;
    int bs = idx >> 9;
    int p  = pos[bs];

    float inv = __expf(-(float)(2 * i) * (9.210340371976184f / 64.0f));
    float ang = (float)p * inv;
    float sn, cs;
    sincosf(ang, &sn, &cs);

    size_t off = (size_t)bs * D_MODEL + h * DK + 2 * i;
    float e = q[off], o = q[off + 1];
    q[off]     = e * cs - o * sn;
    q[off + 1] = e * sn + o * cs;
    e = k[off]; o = k[off + 1];
    k[off]     = e * cs - o * sn;
    k[off + 1] = e * sn + o * cs;
}

// Q (scaled by 1/8) and K -> hi/lo bf16 pairs, same layout as source
__global__ void qk_split_kernel(const float* __restrict__ q, const float* __restrict__ k)
{
    int idx = blockIdx.x * blockDim.x + threadIdx.x;
    if (idx >= NPAIRS) return;
    unsigned* qh = reinterpret_cast<unsigned*>(g_qh);
    unsigned* ql = reinterpret_cast<unsigned*>(g_ql);
    unsigned* kh = reinterpret_cast<unsigned*>(g_kh);
    unsigned* kl = reinterpret_cast<unsigned*>(g_kl);
    float2 xq = ((const float2*)q)[idx];
    unsigned h, l;
    split2(xq.x * 0.125f, xq.y * 0.125f, h, l);
    qh[idx] = h; ql[idx] = l;
    float2 xk = ((const float2*)k)[idx];
    split2(xk.x, xk.y, h, l);
    kh[idx] = h; kl[idx] = l;
}

// V -> transposed per-(b,h) hi/lo bf16: vt[bh][d][s]
__global__ __launch_bounds__(256) void v_transpose_split_kernel(const float* __restrict__ v)
{
    __shared__ float T[32][33];
    const int tid = threadIdx.x;
    const int tx = tid & 31;
    const int ty = tid >> 5;
    const int s0 = blockIdx.x * 32;
    const int d0 = blockIdx.y * 32;
    const int bh = blockIdx.z;
    const int b  = bh >> 4;
    const int h  = bh & 15;

    #pragma unroll
    for (int i = 0; i < 4; i++) {
        int r = ty + i * 8;
        T[r][tx] = v[((size_t)(b * SEQ + s0 + r)) * D_MODEL + h * DK + d0 + tx];
    }
    __syncthreads();
    #pragma unroll
    for (int i = 0; i < 4; i++) {
        int dr = ty + i * 8;
        float x = T[tx][dr];
        __nv_bfloat16 hv = __float2bfloat16_rn(x);
        __nv_bfloat16 lv = __float2bfloat16_rn(x - __bfloat162float(hv));
        size_t off = ((size_t)(bh * DK + d0 + dr)) * SEQ + s0 + tx;
        g_vth[off] = hv;
        g_vtl[off] = lv;
    }
}

// ---------------------------------------------------------------------------
// Flash attention v6 (PASSED R9, ~100us) — mma.sync, ILP-ordered.
// 128 threads = 4 warps; BR=64 queries (m16/warp), BC=64 keys.
// ---------------------------------------------------------------------------
#define FP 72

__global__ __launch_bounds__(128) void flash_mma_kernel(float* __restrict__ o)
{
    __shared__ __align__(16) __nv_bfloat16 Khs[64 * FP];
    __shared__ __align__(16) __nv_bfloat16 Kls[64 * FP];
    __shared__ __align__(16) __nv_bfloat16 Vhs[64 * FP];
    __shared__ __align__(16) __nv_bfloat16 Vls[64 * FP];

    const int bh = blockIdx.y;
    const int b  = bh >> 4;
    const int h  = bh & 15;
    const int qt = (int)gridDim.x - 1 - (int)blockIdx.x;   // long blocks first
    const int q0 = qt * 64;
    const int tid  = threadIdx.x;
    const int warp = tid >> 5;
    const int lane = tid & 31;
    const int g    = lane >> 2;
    const int tig  = lane & 3;
    const int wr0  = q0 + warp * 16;

    unsigned qh[4][4], ql[4][4];
    {
        const size_t r0 = ((size_t)(b * SEQ + wr0 + g)) * D_MODEL + h * DK;
        const size_t r1 = r0 + (size_t)8 * D_MODEL;
        #pragma unroll
        for (int kt = 0; kt < 4; kt++) {
            int d0 = kt * 16 + 2 * tig;
            qh[kt][0] = *(const unsigned*)&g_qh[r0 + d0];
            qh[kt][1] = *(const unsigned*)&g_qh[r1 + d0];
            qh[kt][2] = *(const unsigned*)&g_qh[r0 + d0 + 8];
            qh[kt][3] = *(const unsigned*)&g_qh[r1 + d0 + 8];
            ql[kt][0] = *(const unsigned*)&g_ql[r0 + d0];
            ql[kt][1] = *(const unsigned*)&g_ql[r1 + d0];
            ql[kt][2] = *(const unsigned*)&g_ql[r0 + d0 + 8];
            ql[kt][3] = *(const unsigned*)&g_ql[r1 + d0 + 8];
        }
    }

    float oa[8][4];
    #pragma unroll
    for (int nj = 0; nj < 8; nj++)
        #pragma unroll
        for (int e = 0; e < 4; e++) oa[nj][e] = 0.f;
    float m0 = -1e30f, m1 = -1e30f, l0 = 0.f, l1 = 0.f;

    const int kend = q0 + 64;
    for (int k0 = 0; k0 < kend; k0 += 64) {
        __syncthreads();
        #pragma unroll
        for (int i = 0; i < 4; i++) {
            int c  = tid + i * 128;
            int r  = c >> 3;
            int ch = c & 7;
            size_t ksrc = ((size_t)(b * SEQ + k0 + r)) * D_MODEL + h * DK + ch * 8;
            cpasync16(&Khs[r * FP + ch * 8], g_kh + ksrc);
            cpasync16(&Kls[r * FP + ch * 8], g_kl + ksrc);
            size_t vsrc = ((size_t)(bh * DK + r)) * SEQ + k0 + ch * 8;
            cpasync16(&Vhs[r * FP + ch * 8], g_vth + vsrc);
            cpasync16(&Vls[r * FP + ch * 8], g_vtl + vsrc);
        }
        CP_COMMIT();
        CP_WAIT(0);
        __syncthreads();

        float s[8][4];
        #pragma unroll
        for (int nj = 0; nj < 8; nj++)
            s[nj][0] = s[nj][1] = s[nj][2] = s[nj][3] = 0.f;
        #pragma unroll
        for (int kt = 0; kt < 4; kt++) {
            unsigned kb0[8], kb1[8], kc0[8], kc1[8];
            #pragma unroll
            for (int nj = 0; nj < 8; nj++) {
                int off = (nj * 8 + g) * FP + kt * 16 + 2 * tig;
                kb0[nj] = *(const unsigned*)&Khs[off];
                kb1[nj] = *(const unsigned*)&Khs[off + 8];
                kc0[nj] = *(const unsigned*)&Kls[off];
                kc1[nj] = *(const unsigned*)&Kls[off + 8];
            }
            #pragma unroll
            for (int nj = 0; nj < 8; nj++)
                mma16816(s[nj], qh[kt][0], qh[kt][1], qh[kt][2], qh[kt][3], kb0[nj], kb1[nj]);
            #pragma unroll
            for (int nj = 0; nj < 8; nj++)
                mma16816(s[nj], ql[kt][0], ql[kt][1], ql[kt][2], ql[kt][3], kb0[nj], kb1[nj]);
            #pragma unroll
            for (int nj = 0; nj < 8; nj++)
                mma16816(s[nj], qh[kt][0], qh[kt][1], qh[kt][2], qh[kt][3], kc0[nj], kc1[nj]);
        }

        if (k0 + 63 > wr0 + g) {
            int r0 = wr0 + g, r1 = r0 + 8;
            #pragma unroll
            for (int nj = 0; nj < 8; nj++) {
                int c = k0 + nj * 8 + 2 * tig;
                if (c     > r0) s[nj][0] = -1e30f;
                if (c + 1 > r0) s[nj][1] = -1e30f;
                if (c     > r1) s[nj][2] = -1e30f;
                if (c + 1 > r1) s[nj][3] = -1e30f;
            }
        }

        float rm0 = -1e30f, rm1 = -1e30f;
        #pragma unroll
        for (int nj = 0; nj < 8; nj++) {
            rm0 = fmaxf(rm0, fmaxf(s[nj][0], s[nj][1]));
            rm1 = fmaxf(rm1, fmaxf(s[nj][2], s[nj][3]));
        }
        rm0 = fmaxf(rm0, __shfl_xor_sync(0xffffffffu, rm0, 1));
        rm0 = fmaxf(rm0, __shfl_xor_sync(0xffffffffu, rm0, 2));
        rm1 = fmaxf(rm1, __shfl_xor_sync(0xffffffffu, rm1, 1));
        rm1 = fmaxf(rm1, __shfl_xor_sync(0xffffffffu, rm1, 2));

        float mn0 = fmaxf(m0, rm0), mn1 = fmaxf(m1, rm1);
        float corr0 = __expf(m0 - mn0), corr1 = __expf(m1 - mn1);
        float rs0 = 0.f, rs1 = 0.f;
        #pragma unroll
        for (int nj = 0; nj < 8; nj++) {
            s[nj][0] = __expf(s[nj][0] - mn0);
            s[nj][1] = __expf(s[nj][1] - mn0);
            s[nj][2] = __expf(s[nj][2] - mn1);
            s[nj][3] = __expf(s[nj][3] - mn1);
            rs0 += s[nj][0] + s[nj][1];
            rs1 += s[nj][2] + s[nj][3];
        }
        rs0 += __shfl_xor_sync(0xffffffffu, rs0, 1);
        rs0 += __shfl_xor_sync(0xffffffffu, rs0, 2);
        rs1 += __shfl_xor_sync(0xffffffffu, rs1, 1);
        rs1 += __shfl_xor_sync(0xffffffffu, rs1, 2);
        l0 = l0 * corr0 + rs0;
        l1 = l1 * corr1 + rs1;
        m0 = mn0; m1 = mn1;

        #pragma unroll
        for (int nj = 0; nj < 8; nj++) {
            oa[nj][0] *= corr0; oa[nj][1] *= corr0;
            oa[nj][2] *= corr1; oa[nj][3] *= corr1;
        }

        unsigned pah[4][4], pal[4][4];
        #pragma unroll
        for (int kt = 0; kt < 4; kt++) {
            split2(s[2*kt][0],   s[2*kt][1],   pah[kt][0], pal[kt][0]);
            split2(s[2*kt][2],   s[2*kt][3],   pah[kt][1], pal[kt][1]);
            split2(s[2*kt+1][0], s[2*kt+1][1], pah[kt][2], pal[kt][2]);
            split2(s[2*kt+1][2], s[2*kt+1][3], pah[kt][3], pal[kt][3]);
        }

        #pragma unroll
        for (int kt = 0; kt < 4; kt++) {
            unsigned vb0[8], vb1[8], vc0[8], vc1[8];
            #pragma unroll
            for (int nj = 0; nj < 8; nj++) {
                int off = (nj * 8 + g) * FP + kt * 16 + 2 * tig;
                vb0[nj] = *(const unsigned*)&Vhs[off];
                vb1[nj] = *(const unsigned*)&Vhs[off + 8];
                vc0[nj] = *(const unsigned*)&Vls[off];
                vc1[nj] = *(const unsigned*)&Vls[off + 8];
            }
            #pragma unroll
            for (int nj = 0; nj < 8; nj++)
                mma16816(oa[nj], pah[kt][0], pah[kt][1], pah[kt][2], pah[kt][3], vb0[nj], vb1[nj]);
            #pragma unroll
            for (int nj = 0; nj < 8; nj++)
                mma16816(oa[nj], pal[kt][0], pal[kt][1], pal[kt][2], pal[kt][3], vb0[nj], vb1[nj]);
            #pragma unroll
            for (int nj = 0; nj < 8; nj++)
                mma16816(oa[nj], pah[kt][0], pah[kt][1], pah[kt][2], pah[kt][3], vc0[nj], vc1[nj]);
        }
    }

    {
        float inv0 = 1.0f / l0, inv1 = 1.0f / l1;
        float* or0 = o + ((size_t)(b * SEQ + wr0 + g)) * D_MODEL + h * DK;
        float* or1 = or0 + (size_t)8 * D_MODEL;
        #pragma unroll
        for (int nj = 0; nj < 8; nj++) {
            int d = nj * 8 + 2 * tig;
            *(float2*)(or0 + d) = make_float2(oa[nj][0] * inv0, oa[nj][1] * inv0);
            *(float2*)(or1 + d) = make_float2(oa[nj][2] * inv1, oa[nj][3] * inv1);
        }
    }
}

// ---------------------------------------------------------------------------
// Launch
// ---------------------------------------------------------------------------
extern "C" void kernel_launch(void* const* d_in, const int* in_sizes, int n_in,
                              void* d_out, int out_size)
{
    const float* x  = (const float*)d_in[0];
    const float* Wq = (const float*)d_in[1];
    const float* Wk = (const float*)d_in[2];
    const float* Wv = (const float*)d_in[3];
    const float* Wo = (const float*)d_in[4];
    const int*   tp = (const int*)d_in[5];
    float* out = (float*)d_out;

    float *qp, *kp, *vp, *op;
    cudaGetSymbolAddress((void**)&qp, g_q);
    cudaGetSymbolAddress((void**)&kp, g_k);
    cudaGetSymbolAddress((void**)&vp, g_v);
    cudaGetSymbolAddress((void**)&op, g_o);
    __nv_bfloat16 *xh, *xl, *wh, *wl, *oh, *ol;
    cudaGetSymbolAddress((void**)&xh, g_xh);
    cudaGetSymbolAddress((void**)&xl, g_xl);
    cudaGetSymbolAddress((void**)&wh, g_wh);
    cudaGetSymbolAddress((void**)&wl, g_wl);
    cudaGetSymbolAddress((void**)&oh, g_oh);
    cudaGetSymbolAddress((void**)&ol, g_ol);

    cudaFuncSetAttribute(gemm_mma, cudaFuncAttributeMaxDynamicSharedMemorySize, G_SMEM);

    const size_t WSTRIDE = (size_t)D_MODEL * D_MODEL;

    // 1) split inputs to bf16 hi/lo
    split_kernel<<<(NPAIRS + 255) / 256, 256>>>(x,  xh, xl, NPAIRS);
    split_kernel<<<(WPAIRS + 255) / 256, 256>>>(Wq, wh + 0 * WSTRIDE, wl + 0 * WSTRIDE, WPAIRS);
    split_kernel<<<(WPAIRS + 255) / 256, 256>>>(Wk, wh + 1 * WSTRIDE, wl + 1 * WSTRIDE, WPAIRS);
    split_kernel<<<(WPAIRS + 255) / 256, 256>>>(Wv, wh + 2 * WSTRIDE, wl + 2 * WSTRIDE, WPAIRS);
    split_kernel<<<(WPAIRS + 255) / 256, 256>>>(Wo, wh + 3 * WSTRIDE, wl + 3 * WSTRIDE, WPAIRS);

    // 2) QKV projections (tensor cores)
    dim3 gq(D_MODEL / 128, M_TOT / 128, 3);
    gemm_mma<<<gq, 256, G_SMEM>>>(xh, xl,
        wh + 0 * WSTRIDE, wl + 0 * WSTRIDE, qp,
        wh + 1 * WSTRIDE, wl + 1 * WSTRIDE, kp,
        wh + 2 * WSTRIDE, wl + 2 * WSTRIDE, vp,
        M_TOT, D_MODEL, D_MODEL);

    // 3) RoPE on Q and K
    int npairs_r = BATCH * SEQ * NHEAD * (DK / 2);
    rope_kernel<<<(npairs_r + 255) / 256, 256>>>(qp, kp, tp);

    // 4) attention-side splits
    qk_split_kernel<<<(NPAIRS + 255) / 256, 256>>>(qp, kp);
    v_transpose_split_kernel<<<dim3(SEQ / 32, DK / 32, BATCH * NHEAD), 256>>>(vp);

    // 5) causal flash attention (mma.sync)
    flash_mma_kernel<<<dim3(SEQ / 64, BATCH * NHEAD), 128>>>(op);

    // 6) split O, then output projection (tensor cores)
    split_kernel<<<(NPAIRS + 255) / 256, 256>>>(op, oh, ol, NPAIRS);
    dim3 go(D_MODEL / 128, M_TOT / 128, 1);
    gemm_mma<<<go, 256, G_SMEM>>>(oh, ol,
        wh + 3 * WSTRIDE, wl + 3 * WSTRIDE, out,
        wh + 3 * WSTRIDE, wl + 3 * WSTRIDE, out,
        wh + 3 * WSTRIDE, wl + 3 * WSTRIDE, out,
        M_TOT, D_MODEL, D_MODEL);
}

// round 14
// speedup vs baseline: 4.9079x; 1.0002x over previous
#include <cuda_runtime.h>
#include <cuda_bf16.h>
#include <cstdint>

#define D_MODEL 1024
#define NHEAD   16
#define DK      64
#define BATCH   2
#define SEQ     2048
#define M_TOT   (BATCH*SEQ)   // 4096
#define NPAIRS  (M_TOT*D_MODEL/2)
#define WPAIRS  (D_MODEL*D_MODEL/2)

// Scratch (allocation-free rule: __device__ globals)
__device__ float g_v[(size_t)M_TOT*D_MODEL];
// bf16 hi/lo splits
__device__ __nv_bfloat16 g_xh[(size_t)M_TOT*D_MODEL];
__device__ __nv_bfloat16 g_xl[(size_t)M_TOT*D_MODEL];
__device__ __nv_bfloat16 g_wh[(size_t)4*D_MODEL*D_MODEL];
__device__ __nv_bfloat16 g_wl[(size_t)4*D_MODEL*D_MODEL];
__device__ __nv_bfloat16 g_oh[(size_t)M_TOT*D_MODEL];
__device__ __nv_bfloat16 g_ol[(size_t)M_TOT*D_MODEL];
__device__ __nv_bfloat16 g_qh[(size_t)M_TOT*D_MODEL];
__device__ __nv_bfloat16 g_ql[(size_t)M_TOT*D_MODEL];
__device__ __nv_bfloat16 g_kh[(size_t)M_TOT*D_MODEL];
__device__ __nv_bfloat16 g_kl[(size_t)M_TOT*D_MODEL];
__device__ __nv_bfloat16 g_vth[(size_t)M_TOT*D_MODEL];   // V^T per (b,h): [bh][dim][seq]
__device__ __nv_bfloat16 g_vtl[(size_t)M_TOT*D_MODEL];

// ---------------------------------------------------------------------------
// common helpers
// ---------------------------------------------------------------------------
__device__ __forceinline__ void split2(float x, float y, unsigned& h, unsigned& l)
{
    __nv_bfloat162 hh = __floats2bfloat162_rn(x, y);
    float rx = x - __bfloat162float(hh.x);
    float ry = y - __bfloat162float(hh.y);
    __nv_bfloat162 ll = __floats2bfloat162_rn(rx, ry);
    h = *reinterpret_cast<unsigned*>(&hh);
    l = *reinterpret_cast<unsigned*>(&ll);
}

__device__ __forceinline__ void mma16816(float* c,
    unsigned a0, unsigned a1, unsigned a2, unsigned a3,
    unsigned b0, unsigned b1)
{
    asm volatile(
        "mma.sync.aligned.m16n8k16.row.col.f32.bf16.bf16.f32 "
        "{%0,%1,%2,%3},{%4,%5,%6,%7},{%8,%9},{%0,%1,%2,%3};\n"
        : "+f"(c[0]), "+f"(c[1]), "+f"(c[2]), "+f"(c[3])
        : "r"(a0), "r"(a1), "r"(a2), "r"(a3), "r"(b0), "r"(b1));
}

__device__ __forceinline__ uint32_t smem_u32(const void* p) {
    uint32_t a;
    asm("{ .reg .u64 t; cvta.to.shared.u64 t, %1; cvt.u32.u64 %0, t; }"
        : "=r"(a) : "l"(p));
    return a;
}
__device__ __forceinline__ void cp16r(uint32_t saddr, const void* gsrc)
{
    asm volatile("cp.async.cg.shared.global [%0], [%1], 16;\n" :: "r"(saddr), "l"(gsrc));
}
__device__ __forceinline__ void cpasync16(void* smem_dst, const void* gsrc)
{
    unsigned s = (unsigned)__cvta_generic_to_shared(smem_dst);
    asm volatile("cp.async.cg.shared.global [%0], [%1], 16;\n" :: "r"(s), "l"(gsrc));
}
#define CP_COMMIT() asm volatile("cp.async.commit_group;\n" ::: "memory")
#define CP_WAIT(n)  asm volatile("cp.async.wait_group %0;\n" :: "n"(n) : "memory")

// ---------------------------------------------------------------------------
// generic fp32 -> bf16 hi/lo split
// ---------------------------------------------------------------------------
__global__ void split_kernel(const float* __restrict__ src,
                             __nv_bfloat16* __restrict__ h,
                             __nv_bfloat16* __restrict__ l, int npairs)
{
    int idx = blockIdx.x * blockDim.x + threadIdx.x;
    if (idx >= npairs) return;
    float2 x = ((const float2*)src)[idx];
    unsigned hh, ll;
    split2(x.x, x.y, hh, ll);
    ((unsigned*)h)[idx] = hh;
    ((unsigned*)l)[idx] = ll;
}

// ---------------------------------------------------------------------------
// GEMM via mma.sync split-bf16: C[M,N] = A[M,K] * B[N,K]^T.
// 128x128 block tile, 256 threads = 8 warps (4x2), each warp m32 x n64.
// BK=32 chunks double-buffered (80KB smem -> 2 CTAs/SM).
// MODE 0: QKV fused epilogue — z=0: RoPE+scale+split->qh/ql; z=1: RoPE+split
//         ->kh/kl; z=2: fp32 V. MODE 1: plain fp32 writeback to Cv.
// ---------------------------------------------------------------------------
#define GP2     40                        // bf16 pitch (80B rows)
#define G2_ARR  10240                     // bytes per array (128*80)
#define G2_BUF  (4*G2_ARR)                // 40960 per buffer
#define G2_SMEM (2*G2_BUF)                // 81920

template<int MODE>
__global__ __launch_bounds__(256, 2) void gemm_mma(
    const __nv_bfloat16* __restrict__ Ah, const __nv_bfloat16* __restrict__ Al,
    const __nv_bfloat16* Bh0, const __nv_bfloat16* Bl0,
    const __nv_bfloat16* Bh1, const __nv_bfloat16* Bl1,
    const __nv_bfloat16* Bh2, const __nv_bfloat16* Bl2,
    float* Cv, const int* __restrict__ pos,
    int M, int N, int K)
{
    extern __shared__ __align__(16) char gsm[];
    const __nv_bfloat16 *Bh, *Bl;
    if (blockIdx.z == 0)      { Bh = Bh0; Bl = Bl0; }
    else if (blockIdx.z == 1) { Bh = Bh1; Bl = Bl1; }
    else                      { Bh = Bh2; Bl = Bl2; }

    const uint32_t sb = smem_u32(gsm);
    const __nv_bfloat16* sm = (const __nv_bfloat16*)gsm;

    const int m0 = blockIdx.y * 128;
    const int n0 = blockIdx.x * 128;
    const int tid  = threadIdx.x;
    const int warp = tid >> 5;
    const int lane = tid & 31;
    const int g    = lane >> 2;
    const int tig  = lane & 3;
    const int wm   = warp >> 1;
    const int wn   = warp & 1;
    const int nk   = K >> 5;              // chunks of 32

    float c[2][8][4];
    #pragma unroll
    for (int m = 0; m < 2; m++)
        #pragma unroll
        for (int n = 0; n < 8; n++)
            c[m][n][0] = c[m][n][1] = c[m][n][2] = c[m][n][3] = 0.f;

    #define G_STAGE(kc, bi) do {                                               \
        uint32_t bb = sb + (bi) * G2_BUF;                                      \
        _Pragma("unroll")                                                      \
        for (int i = 0; i < 2; i++) {                                          \
            int idx = tid + i * 256;                                           \
            int r = idx >> 2, ch = idx & 3;                                    \
            uint32_t d = r * 80 + ch * 16;                                     \
            size_t as = (size_t)(m0 + r) * K + (kc) * 32 + ch * 8;             \
            cp16r(bb + d,             Ah + as);                                \
            cp16r(bb + G2_ARR + d,    Al + as);                                \
            size_t bs = (size_t)(n0 + r) * K + (kc) * 32 + ch * 8;             \
            cp16r(bb + 2*G2_ARR + d,  Bh + bs);                                \
            cp16r(bb + 3*G2_ARR + d,  Bl + bs);                                \
        }                                                                      \
        CP_COMMIT();                                                           \
    } while (0)

    G_STAGE(0, 0);

    for (int kc = 0; kc < nk; kc++) {
        if (kc + 1 < nk) { G_STAGE(kc + 1, (kc + 1) & 1); CP_WAIT(1); }
        else             { CP_WAIT(0); }
        __syncthreads();

        const __nv_bfloat16* sAh = sm + (kc & 1) * (G2_BUF / 2);
        const __nv_bfloat16* sAl = sAh + G2_ARR / 2;
        const __nv_bfloat16* sBh = sAh + G2_ARR;
        const __nv_bfloat16* sBl = sAh + 3 * (G2_ARR / 2);

        #pragma unroll
        for (int kt = 0; kt < 2; kt++) {
            const int cb = kt * 16 + 2 * tig;
            unsigned ah[2][4], al[2][4];
            #pragma unroll
            for (int m = 0; m < 2; m++) {
                int rw = wm * 32 + m * 16;
                ah[m][0] = *(const unsigned*)&sAh[(rw + g)     * GP2 + cb];
                ah[m][1] = *(const unsigned*)&sAh[(rw + g + 8) * GP2 + cb];
                ah[m][2] = *(const unsigned*)&sAh[(rw + g)     * GP2 + cb + 8];
                ah[m][3] = *(const unsigned*)&sAh[(rw + g + 8) * GP2 + cb + 8];
                al[m][0] = *(const unsigned*)&sAl[(rw + g)     * GP2 + cb];
                al[m][1] = *(const unsigned*)&sAl[(rw + g + 8) * GP2 + cb];
                al[m][2] = *(const unsigned*)&sAl[(rw + g)     * GP2 + cb + 8];
                al[m][3] = *(const unsigned*)&sAl[(rw + g + 8) * GP2 + cb + 8];
            }
            unsigned bh0[8], bh1[8], bl0[8], bl1[8];
            #pragma unroll
            for (int n = 0; n < 8; n++) {
                int off = (wn * 64 + n * 8 + g) * GP2 + cb;
                bh0[n] = *(const unsigned*)&sBh[off];
                bh1[n] = *(const unsigned*)&sBh[off + 8];
                bl0[n] = *(const unsigned*)&sBl[off];
                bl1[n] = *(const unsigned*)&sBl[off + 8];
            }
            #pragma unroll
            for (int m = 0; m < 2; m++)
                #pragma unroll
                for (int n = 0; n < 8; n++)
                    mma16816(c[m][n], ah[m][0], ah[m][1], ah[m][2], ah[m][3], bh0[n], bh1[n]);
            #pragma unroll
            for (int m = 0; m < 2; m++)
                #pragma unroll
                for (int n = 0; n < 8; n++)
                    mma16816(c[m][n], al[m][0], al[m][1], al[m][2], al[m][3], bh0[n], bh1[n]);
            #pragma unroll
            for (int m = 0; m < 2; m++)
                #pragma unroll
                for (int n = 0; n < 8; n++)
                    mma16816(c[m][n], ah[m][0], ah[m][1], ah[m][2], ah[m][3], bl0[n], bl1[n]);
        }
        __syncthreads();
    }
    #undef G_STAGE

    // ---- epilogue ----
    if (MODE == 1 || blockIdx.z == 2) {
        #pragma unroll
        for (int m = 0; m < 2; m++) {
            float* cr = Cv + (size_t)(m0 + wm * 32 + m * 16 + g) * N + n0 + wn * 64 + 2 * tig;
            #pragma unroll
            for (int n = 0; n < 8; n++) {
                *(float2*)(cr + n * 8)         = make_float2(c[m][n][0], c[m][n][1]);
                *(float2*)(cr + 8 * N + n * 8) = make_float2(c[m][n][2], c[m][n][3]);
            }
        }
    } else {
        // fused RoPE + (scale) + hi/lo split for Q (z=0) or K (z=1)
        const bool isQ = (blockIdx.z == 0);
        unsigned* dh = (unsigned*)(isQ ? g_qh : g_kh);
        unsigned* dl = (unsigned*)(isQ ? g_ql : g_kl);
        const float sc = isQ ? 0.125f : 1.0f;
        #pragma unroll
        for (int m = 0; m < 2; m++) {
            int r0 = m0 + wm * 32 + m * 16 + g;
            float p0 = (float)pos[r0];
            float p1 = (float)pos[r0 + 8];
            #pragma unroll
            for (int n = 0; n < 8; n++) {
                int c0 = n0 + wn * 64 + n * 8 + 2 * tig;     // even column
                int i = (c0 & 63) >> 1;
                float inv = __expf(-(float)(2 * i) * (9.210340371976184f / 64.0f));
                float s0, cs0, s1, cs1;
                sincosf(p0 * inv, &s0, &cs0);
                sincosf(p1 * inv, &s1, &cs1);
                unsigned hh, ll;
                float e = c[m][n][0], o_ = c[m][n][1];
                split2((e * cs0 - o_ * s0) * sc, (e * s0 + o_ * cs0) * sc, hh, ll);
                size_t ix = ((size_t)r0 * D_MODEL + c0) >> 1;
                dh[ix] = hh; dl[ix] = ll;
                e = c[m][n][2]; o_ = c[m][n][3];
                split2((e * cs1 - o_ * s1) * sc, (e * s1 + o_ * cs1) * sc, hh, ll);
                ix = ((size_t)(r0 + 8) * D_MODEL + c0) >> 1;
                dh[ix] = hh; dl[ix] = ll;
            }
        }
    }
}

// ---------------------------------------------------------------------------
// V -> transposed per-(b,h) hi/lo bf16: vt[bh][d][s]
// ---------------------------------------------------------------------------
__global__ __launch_bounds__(256) void v_transpose_split_kernel(const float* __restrict__ v)
{
    __shared__ float T[32][33];
    const int tid = threadIdx.x;
    const int tx = tid & 31;
    const int ty = tid >> 5;
    const int s0 = blockIdx.x * 32;
    const int d0 = blockIdx.y * 32;
    const int bh = blockIdx.z;
    const int b  = bh >> 4;
    const int h  = bh & 15;

    #pragma unroll
    for (int i = 0; i < 4; i++) {
        int r = ty + i * 8;
        T[r][tx] = v[((size_t)(b * SEQ + s0 + r)) * D_MODEL + h * DK + d0 + tx];
    }
    __syncthreads();
    #pragma unroll
    for (int i = 0; i < 4; i++) {
        int dr = ty + i * 8;
        float x = T[tx][dr];
        __nv_bfloat16 hv = __float2bfloat16_rn(x);
        __nv_bfloat16 lv = __float2bfloat16_rn(x - __bfloat162float(hv));
        size_t off = ((size_t)(bh * DK + d0 + dr)) * SEQ + s0 + tx;
        g_vth[off] = hv;
        g_vtl[off] = lv;
    }
}

// ---------------------------------------------------------------------------
// Flash attention (mma.sync, ILP-ordered). Epilogue writes oh/ol directly.
// 128 threads = 4 warps; BR=64 queries (m16/warp), BC=64 keys.
// ---------------------------------------------------------------------------
#define FP 72

__global__ __launch_bounds__(128) void flash_mma_kernel()
{
    __shared__ __align__(16) __nv_bfloat16 Khs[64 * FP];
    __shared__ __align__(16) __nv_bfloat16 Kls[64 * FP];
    __shared__ __align__(16) __nv_bfloat16 Vhs[64 * FP];
    __shared__ __align__(16) __nv_bfloat16 Vls[64 * FP];

    const int bh = blockIdx.y;
    const int b  = bh >> 4;
    const int h  = bh & 15;
    const int qt = (int)gridDim.x - 1 - (int)blockIdx.x;   // long blocks first
    const int q0 = qt * 64;
    const int tid  = threadIdx.x;
    const int warp = tid >> 5;
    const int lane = tid & 31;
    const int g    = lane >> 2;
    const int tig  = lane & 3;
    const int wr0  = q0 + warp * 16;

    unsigned qh[4][4], ql[4][4];
    {
        const size_t r0 = ((size_t)(b * SEQ + wr0 + g)) * D_MODEL + h * DK;
        const size_t r1 = r0 + (size_t)8 * D_MODEL;
        #pragma unroll
        for (int kt = 0; kt < 4; kt++) {
            int d0 = kt * 16 + 2 * tig;
            qh[kt][0] = *(const unsigned*)&g_qh[r0 + d0];
            qh[kt][1] = *(const unsigned*)&g_qh[r1 + d0];
            qh[kt][2] = *(const unsigned*)&g_qh[r0 + d0 + 8];
            qh[kt][3] = *(const unsigned*)&g_qh[r1 + d0 + 8];
            ql[kt][0] = *(const unsigned*)&g_ql[r0 + d0];
            ql[kt][1] = *(const unsigned*)&g_ql[r1 + d0];
            ql[kt][2] = *(const unsigned*)&g_ql[r0 + d0 + 8];
            ql[kt][3] = *(const unsigned*)&g_ql[r1 + d0 + 8];
        }
    }

    float oa[8][4];
    #pragma unroll
    for (int nj = 0; nj < 8; nj++)
        #pragma unroll
        for (int e = 0; e < 4; e++) oa[nj][e] = 0.f;
    float m0 = -1e30f, m1 = -1e30f, l0 = 0.f, l1 = 0.f;

    const int kend = q0 + 64;
    for (int k0 = 0; k0 < kend; k0 += 64) {
        __syncthreads();
        #pragma unroll
        for (int i = 0; i < 4; i++) {
            int c  = tid + i * 128;
            int r  = c >> 3;
            int ch = c & 7;
            size_t ksrc = ((size_t)(b * SEQ + k0 + r)) * D_MODEL + h * DK + ch * 8;
            cpasync16(&Khs[r * FP + ch * 8], g_kh + ksrc);
            cpasync16(&Kls[r * FP + ch * 8], g_kl + ksrc);
            size_t vsrc = ((size_t)(bh * DK + r)) * SEQ + k0 + ch * 8;
            cpasync16(&Vhs[r * FP + ch * 8], g_vth + vsrc);
            cpasync16(&Vls[r * FP + ch * 8], g_vtl + vsrc);
        }
        CP_COMMIT();
        CP_WAIT(0);
        __syncthreads();

        float s[8][4];
        #pragma unroll
        for (int nj = 0; nj < 8; nj++)
            s[nj][0] = s[nj][1] = s[nj][2] = s[nj][3] = 0.f;
        #pragma unroll
        for (int kt = 0; kt < 4; kt++) {
            unsigned kb0[8], kb1[8], kc0[8], kc1[8];
            #pragma unroll
            for (int nj = 0; nj < 8; nj++) {
                int off = (nj * 8 + g) * FP + kt * 16 + 2 * tig;
                kb0[nj] = *(const unsigned*)&Khs[off];
                kb1[nj] = *(const unsigned*)&Khs[off + 8];
                kc0[nj] = *(const unsigned*)&Kls[off];
                kc1[nj] = *(const unsigned*)&Kls[off + 8];
            }
            #pragma unroll
            for (int nj = 0; nj < 8; nj++)
                mma16816(s[nj], qh[kt][0], qh[kt][1], qh[kt][2], qh[kt][3], kb0[nj], kb1[nj]);
            #pragma unroll
            for (int nj = 0; nj < 8; nj++)
                mma16816(s[nj], ql[kt][0], ql[kt][1], ql[kt][2], ql[kt][3], kb0[nj], kb1[nj]);
            #pragma unroll
            for (int nj = 0; nj < 8; nj++)
                mma16816(s[nj], qh[kt][0], qh[kt][1], qh[kt][2], qh[kt][3], kc0[nj], kc1[nj]);
        }

        if (k0 + 63 > wr0 + g) {
            int r0 = wr0 + g, r1 = r0 + 8;
            #pragma unroll
            for (int nj = 0; nj < 8; nj++) {
                int c = k0 + nj * 8 + 2 * tig;
                if (c     > r0) s[nj][0] = -1e30f;
                if (c + 1 > r0) s[nj][1] = -1e30f;
                if (c     > r1) s[nj][2] = -1e30f;
                if (c + 1 > r1) s[nj][3] = -1e30f;
            }
        }

        float rm0 = -1e30f, rm1 = -1e30f;
        #pragma unroll
        for (int nj = 0; nj < 8; nj++) {
            rm0 = fmaxf(rm0, fmaxf(s[nj][0], s[nj][1]));
            rm1 = fmaxf(rm1, fmaxf(s[nj][2], s[nj][3]));
        }
        rm0 = fmaxf(rm0, __shfl_xor_sync(0xffffffffu, rm0, 1));
        rm0 = fmaxf(rm0, __shfl_xor_sync(0xffffffffu, rm0, 2));
        rm1 = fmaxf(rm1, __shfl_xor_sync(0xffffffffu, rm1, 1));
        rm1 = fmaxf(rm1, __shfl_xor_sync(0xffffffffu, rm1, 2));

        float mn0 = fmaxf(m0, rm0), mn1 = fmaxf(m1, rm1);
        float corr0 = __expf(m0 - mn0), corr1 = __expf(m1 - mn1);
        float rs0 = 0.f, rs1 = 0.f;
        #pragma unroll
        for (int nj = 0; nj < 8; nj++) {
            s[nj][0] = __expf(s[nj][0] - mn0);
            s[nj][1] = __expf(s[nj][1] - mn0);
            s[nj][2] = __expf(s[nj][2] - mn1);
            s[nj][3] = __expf(s[nj][3] - mn1);
            rs0 += s[nj][0] + s[nj][1];
            rs1 += s[nj][2] + s[nj][3];
        }
        rs0 += __shfl_xor_sync(0xffffffffu, rs0, 1);
        rs0 += __shfl_xor_sync(0xffffffffu, rs0, 2);
        rs1 += __shfl_xor_sync(0xffffffffu, rs1, 1);
        rs1 += __shfl_xor_sync(0xffffffffu, rs1, 2);
        l0 = l0 * corr0 + rs0;
        l1 = l1 * corr1 + rs1;
        m0 = mn0; m1 = mn1;

        #pragma unroll
        for (int nj = 0; nj < 8; nj++) {
            oa[nj][0] *= corr0; oa[nj][1] *= corr0;
            oa[nj][2] *= corr1; oa[nj][3] *= corr1;
        }

        unsigned pah[4][4], pal[4][4];
        #pragma unroll
        for (int kt = 0; kt < 4; kt++) {
            split2(s[2*kt][0],   s[2*kt][1],   pah[kt][0], pal[kt][0]);
            split2(s[2*kt][2],   s[2*kt][3],   pah[kt][1], pal[kt][1]);
            split2(s[2*kt+1][0], s[2*kt+1][1], pah[kt][2], pal[kt][2]);
            split2(s[2*kt+1][2], s[2*kt+1][3], pah[kt][3], pal[kt][3]);
        }

        #pragma unroll
        for (int kt = 0; kt < 4; kt++) {
            unsigned vb0[8], vb1[8], vc0[8], vc1[8];
            #pragma unroll
            for (int nj = 0; nj < 8; nj++) {
                int off = (nj * 8 + g) * FP + kt * 16 + 2 * tig;
                vb0[nj] = *(const unsigned*)&Vhs[off];
                vb1[nj] = *(const unsigned*)&Vhs[off + 8];
                vc0[nj] = *(const unsigned*)&Vls[off];
                vc1[nj] = *(const unsigned*)&Vls[off + 8];
            }
            #pragma unroll
            for (int nj = 0; nj < 8; nj++)
                mma16816(oa[nj], pah[kt][0], pah[kt][1], pah[kt][2], pah[kt][3], vb0[nj], vb1[nj]);
            #pragma unroll
            for (int nj = 0; nj < 8; nj++)
                mma16816(oa[nj], pal[kt][0], pal[kt][1], pal[kt][2], pal[kt][3], vb0[nj], vb1[nj]);
            #pragma unroll
            for (int nj = 0; nj < 8; nj++)
                mma16816(oa[nj], pah[kt][0], pah[kt][1], pah[kt][2], pah[kt][3], vc0[nj], vc1[nj]);
        }
    }

    // ---- epilogue: normalize and write hi/lo bf16 splits of O ----
    {
        float inv0 = 1.0f / l0, inv1 = 1.0f / l1;
        unsigned* dh = (unsigned*)g_oh;
        unsigned* dl = (unsigned*)g_ol;
        const size_t row0 = (size_t)(b * SEQ + wr0 + g);
        #pragma unroll
        for (int nj = 0; nj < 8; nj++) {
            int d = h * DK + nj * 8 + 2 * tig;       // even
            unsigned hh, ll;
            split2(oa[nj][0] * inv0, oa[nj][1] * inv0, hh, ll);
            size_t ix = (row0 * D_MODEL + d) >> 1;
            dh[ix] = hh; dl[ix] = ll;
            split2(oa[nj][2] * inv1, oa[nj][3] * inv1, hh, ll);
            ix = ((row0 + 8) * D_MODEL + d) >> 1;
            dh[ix] = hh; dl[ix] = ll;
        }
    }
}

// ---------------------------------------------------------------------------
// Launch
// ---------------------------------------------------------------------------
extern "C" void kernel_launch(void* const* d_in, const int* in_sizes, int n_in,
                              void* d_out, int out_size)
{
    const float* x  = (const float*)d_in[0];
    const float* Wq = (const float*)d_in[1];
    const float* Wk = (const float*)d_in[2];
    const float* Wv = (const float*)d_in[3];
    const float* Wo = (const float*)d_in[4];
    const int*   tp = (const int*)d_in[5];
    float* out = (float*)d_out;

    float* vp;
    cudaGetSymbolAddress((void**)&vp, g_v);
    __nv_bfloat16 *xh, *xl, *wh, *wl, *oh, *ol;
    cudaGetSymbolAddress((void**)&xh, g_xh);
    cudaGetSymbolAddress((void**)&xl, g_xl);
    cudaGetSymbolAddress((void**)&wh, g_wh);
    cudaGetSymbolAddress((void**)&wl, g_wl);
    cudaGetSymbolAddress((void**)&oh, g_oh);
    cudaGetSymbolAddress((void**)&ol, g_ol);

    cudaFuncSetAttribute(gemm_mma<0>, cudaFuncAttributeMaxDynamicSharedMemorySize, G2_SMEM);
    cudaFuncSetAttribute(gemm_mma<1>, cudaFuncAttributeMaxDynamicSharedMemorySize, G2_SMEM);

    const size_t WSTRIDE = (size_t)D_MODEL * D_MODEL;

    // 1) split inputs to bf16 hi/lo
    split_kernel<<<(NPAIRS + 255) / 256, 256>>>(x,  xh, xl, NPAIRS);
    split_kernel<<<(WPAIRS + 255) / 256, 256>>>(Wq, wh + 0 * WSTRIDE, wl + 0 * WSTRIDE, WPAIRS);
    split_kernel<<<(WPAIRS + 255) / 256, 256>>>(Wk, wh + 1 * WSTRIDE, wl + 1 * WSTRIDE, WPAIRS);
    split_kernel<<<(WPAIRS + 255) / 256, 256>>>(Wv, wh + 2 * WSTRIDE, wl + 2 * WSTRIDE, WPAIRS);
    split_kernel<<<(WPAIRS + 255) / 256, 256>>>(Wo, wh + 3 * WSTRIDE, wl + 3 * WSTRIDE, WPAIRS);

    // 2) QKV projections with fused RoPE + split epilogue
    dim3 gq(D_MODEL / 128, M_TOT / 128, 3);
    gemm_mma<0><<<gq, 256, G2_SMEM>>>(xh, xl,
        wh + 0 * WSTRIDE, wl + 0 * WSTRIDE,
        wh + 1 * WSTRIDE, wl + 1 * WSTRIDE,
        wh + 2 * WSTRIDE, wl + 2 * WSTRIDE,
        vp, tp, M_TOT, D_MODEL, D_MODEL);

    // 3) V transpose + split
    v_transpose_split_kernel<<<dim3(SEQ / 32, DK / 32, BATCH * NHEAD), 256>>>(vp);

    // 4) causal flash attention (writes oh/ol directly)
    flash_mma_kernel<<<dim3(SEQ / 64, BATCH * NHEAD), 128>>>();

    // 5) output projection
    dim3 go(D_MODEL / 128, M_TOT / 128, 1);
    gemm_mma<1><<<go, 256, G2_SMEM>>>(oh, ol,
        wh + 3 * WSTRIDE, wl + 3 * WSTRIDE,
        wh + 3 * WSTRIDE, wl + 3 * WSTRIDE,
        wh + 3 * WSTRIDE, wl + 3 * WSTRIDE,
        out, tp, M_TOT, D_MODEL, D_MODEL);
}

// round 15
// speedup vs baseline: 4.9566x; 1.0099x over previous
#include <cuda_runtime.h>
#include <cuda_bf16.h>
#include <cstdint>

#define D_MODEL 1024
#define NHEAD   16
#define DK      64
#define BATCH   2
#define SEQ     2048
#define M_TOT   (BATCH*SEQ)   // 4096
#define NPAIRS  (M_TOT*D_MODEL/2)
#define WPAIRS  (D_MODEL*D_MODEL/2)

// Scratch (allocation-free rule: __device__ globals)
__device__ float g_v[(size_t)M_TOT*D_MODEL];
// bf16 hi/lo splits
__device__ __nv_bfloat16 g_xh[(size_t)M_TOT*D_MODEL];
__device__ __nv_bfloat16 g_xl[(size_t)M_TOT*D_MODEL];
__device__ __nv_bfloat16 g_wh[(size_t)4*D_MODEL*D_MODEL];
__device__ __nv_bfloat16 g_wl[(size_t)4*D_MODEL*D_MODEL];
__device__ __nv_bfloat16 g_oh[(size_t)M_TOT*D_MODEL];
__device__ __nv_bfloat16 g_ol[(size_t)M_TOT*D_MODEL];
__device__ __nv_bfloat16 g_qh[(size_t)M_TOT*D_MODEL];
__device__ __nv_bfloat16 g_ql[(size_t)M_TOT*D_MODEL];
__device__ __nv_bfloat16 g_kh[(size_t)M_TOT*D_MODEL];
__device__ __nv_bfloat16 g_kl[(size_t)M_TOT*D_MODEL];
__device__ __nv_bfloat16 g_vth[(size_t)M_TOT*D_MODEL];   // V^T per (b,h): [bh][dim][seq]
__device__ __nv_bfloat16 g_vtl[(size_t)M_TOT*D_MODEL];

// ---------------------------------------------------------------------------
// common helpers
// ---------------------------------------------------------------------------
__device__ __forceinline__ void split2(float x, float y, unsigned& h, unsigned& l)
{
    __nv_bfloat162 hh = __floats2bfloat162_rn(x, y);
    float rx = x - __bfloat162float(hh.x);
    float ry = y - __bfloat162float(hh.y);
    __nv_bfloat162 ll = __floats2bfloat162_rn(rx, ry);
    h = *reinterpret_cast<unsigned*>(&hh);
    l = *reinterpret_cast<unsigned*>(&ll);
}

__device__ __forceinline__ void mma16816(float* c,
    unsigned a0, unsigned a1, unsigned a2, unsigned a3,
    unsigned b0, unsigned b1)
{
    asm volatile(
        "mma.sync.aligned.m16n8k16.row.col.f32.bf16.bf16.f32 "
        "{%0,%1,%2,%3},{%4,%5,%6,%7},{%8,%9},{%0,%1,%2,%3};\n"
        : "+f"(c[0]), "+f"(c[1]), "+f"(c[2]), "+f"(c[3])
        : "r"(a0), "r"(a1), "r"(a2), "r"(a3), "r"(b0), "r"(b1));
}

__device__ __forceinline__ uint32_t smem_u32(const void* p) {
    uint32_t a;
    asm("{ .reg .u64 t; cvta.to.shared.u64 t, %1; cvt.u32.u64 %0, t; }"
        : "=r"(a) : "l"(p));
    return a;
}
__device__ __forceinline__ void cp16r(uint32_t saddr, const void* gsrc)
{
    asm volatile("cp.async.cg.shared.global [%0], [%1], 16;\n" :: "r"(saddr), "l"(gsrc));
}
__device__ __forceinline__ void cpasync16(void* smem_dst, const void* gsrc)
{
    unsigned s = (unsigned)__cvta_generic_to_shared(smem_dst);
    asm volatile("cp.async.cg.shared.global [%0], [%1], 16;\n" :: "r"(s), "l"(gsrc));
}
#define CP_COMMIT() asm volatile("cp.async.commit_group;\n" ::: "memory")
#define CP_WAIT(n)  asm volatile("cp.async.wait_group %0;\n" :: "n"(n) : "memory")

// ---------------------------------------------------------------------------
// fp32 -> bf16 hi/lo split, 4 pairs per thread (float4 in, uint4 out)
// ---------------------------------------------------------------------------
__global__ void split_kernel(const float* __restrict__ src,
                             __nv_bfloat16* __restrict__ h,
                             __nv_bfloat16* __restrict__ l, int npairs)
{
    int p0 = (blockIdx.x * blockDim.x + threadIdx.x) * 4;   // first pair index
    if (p0 >= npairs) return;
    float4 a = ((const float4*)src)[p0 >> 1];
    float4 b = ((const float4*)src)[(p0 >> 1) + 1];
    uint4 hh, ll;
    split2(a.x, a.y, hh.x, ll.x);
    split2(a.z, a.w, hh.y, ll.y);
    split2(b.x, b.y, hh.z, ll.z);
    split2(b.z, b.w, hh.w, ll.w);
    ((uint4*)h)[p0 >> 2] = hh;
    ((uint4*)l)[p0 >> 2] = ll;
}

// ---------------------------------------------------------------------------
// GEMM via mma.sync split-bf16: C[M,N] = A[M,K] * B[N,K]^T.
// 128x256 block tile, 512 threads = 16 warps (4m x 4n), each warp m32 x n64.
// BK=32 chunks double-buffered (120KB smem, 1 CTA/SM, 4 warps/SMSP).
// MODE 0: QKV fused epilogue — z=0: RoPE+scale+split->qh/ql; z=1: RoPE+split
//         ->kh/kl; z=2: fp32 V. MODE 1: plain fp32 writeback to Cv.
// ---------------------------------------------------------------------------
#define GP2     40                        // bf16 pitch (80B rows)
#define A3_ARR  10240                     // bytes: 128 rows * 80
#define B3_ARR  20480                     // bytes: 256 rows * 80
#define G3_BUF  (2*A3_ARR + 2*B3_ARR)     // 61440 per buffer
#define G3_SMEM (2*G3_BUF)                // 122880

template<int MODE>
__global__ __launch_bounds__(512) void gemm_mma(
    const __nv_bfloat16* __restrict__ Ah, const __nv_bfloat16* __restrict__ Al,
    const __nv_bfloat16* Bh0, const __nv_bfloat16* Bl0,
    const __nv_bfloat16* Bh1, const __nv_bfloat16* Bl1,
    const __nv_bfloat16* Bh2, const __nv_bfloat16* Bl2,
    float* Cv, const int* __restrict__ pos,
    int M, int N, int K)
{
    extern __shared__ __align__(16) char gsm[];
    const __nv_bfloat16 *Bh, *Bl;
    if (blockIdx.z == 0)      { Bh = Bh0; Bl = Bl0; }
    else if (blockIdx.z == 1) { Bh = Bh1; Bl = Bl1; }
    else                      { Bh = Bh2; Bl = Bl2; }

    const uint32_t sb = smem_u32(gsm);
    const __nv_bfloat16* sm = (const __nv_bfloat16*)gsm;

    const int m0 = blockIdx.y * 128;
    const int n0 = blockIdx.x * 256;
    const int tid  = threadIdx.x;
    const int warp = tid >> 5;
    const int lane = tid & 31;
    const int g    = lane >> 2;
    const int tig  = lane & 3;
    const int wm   = warp >> 2;           // 0..3 -> m offset 32*wm
    const int wn   = warp & 3;            // 0..3 -> n offset 64*wn
    const int nk   = K >> 5;              // chunks of 32

    float c[2][8][4];
    #pragma unroll
    for (int m = 0; m < 2; m++)
        #pragma unroll
        for (int n = 0; n < 8; n++)
            c[m][n][0] = c[m][n][1] = c[m][n][2] = c[m][n][3] = 0.f;

    #define G_STAGE(kc, bi) do {                                               \
        uint32_t bb = sb + (bi) * G3_BUF;                                      \
        {                                                                      \
            int r = tid >> 2, ch = tid & 3;                                    \
            uint32_t d = r * 80 + ch * 16;                                     \
            size_t as = (size_t)(m0 + r) * K + (kc) * 32 + ch * 8;             \
            cp16r(bb + d,          Ah + as);                                   \
            cp16r(bb + A3_ARR + d, Al + as);                                   \
        }                                                                      \
        _Pragma("unroll")                                                      \
        for (int i = 0; i < 2; i++) {                                          \
            int idx = tid + i * 512;                                           \
            int r = idx >> 2, ch = idx & 3;                                    \
            uint32_t d = r * 80 + ch * 16;                                     \
            size_t bs = (size_t)(n0 + r) * K + (kc) * 32 + ch * 8;             \
            cp16r(bb + 2*A3_ARR + d,          Bh + bs);                        \
            cp16r(bb + 2*A3_ARR + B3_ARR + d, Bl + bs);                        \
        }                                                                      \
        CP_COMMIT();                                                           \
    } while (0)

    G_STAGE(0, 0);

    for (int kc = 0; kc < nk; kc++) {
        if (kc + 1 < nk) { G_STAGE(kc + 1, (kc + 1) & 1); CP_WAIT(1); }
        else             { CP_WAIT(0); }
        __syncthreads();

        const __nv_bfloat16* sAh = sm + (kc & 1) * (G3_BUF / 2);
        const __nv_bfloat16* sAl = sAh + A3_ARR / 2;
        const __nv_bfloat16* sBh = sAh + A3_ARR;             // 2*A3_ARR bytes
        const __nv_bfloat16* sBl = sBh + B3_ARR / 2;

        #pragma unroll
        for (int kt = 0; kt < 2; kt++) {
            const int cb = kt * 16 + 2 * tig;
            unsigned ah[2][4], al[2][4];
            #pragma unroll
            for (int m = 0; m < 2; m++) {
                int rw = wm * 32 + m * 16;
                ah[m][0] = *(const unsigned*)&sAh[(rw + g)     * GP2 + cb];
                ah[m][1] = *(const unsigned*)&sAh[(rw + g + 8) * GP2 + cb];
                ah[m][2] = *(const unsigned*)&sAh[(rw + g)     * GP2 + cb + 8];
                ah[m][3] = *(const unsigned*)&sAh[(rw + g + 8) * GP2 + cb + 8];
                al[m][0] = *(const unsigned*)&sAl[(rw + g)     * GP2 + cb];
                al[m][1] = *(const unsigned*)&sAl[(rw + g + 8) * GP2 + cb];
                al[m][2] = *(const unsigned*)&sAl[(rw + g)     * GP2 + cb + 8];
                al[m][3] = *(const unsigned*)&sAl[(rw + g + 8) * GP2 + cb + 8];
            }
            unsigned bh0[8], bh1[8], bl0[8], bl1[8];
            #pragma unroll
            for (int n = 0; n < 8; n++) {
                int off = (wn * 64 + n * 8 + g) * GP2 + cb;
                bh0[n] = *(const unsigned*)&sBh[off];
                bh1[n] = *(const unsigned*)&sBh[off + 8];
                bl0[n] = *(const unsigned*)&sBl[off];
                bl1[n] = *(const unsigned*)&sBl[off + 8];
            }
            #pragma unroll
            for (int m = 0; m < 2; m++)
                #pragma unroll
                for (int n = 0; n < 8; n++)
                    mma16816(c[m][n], ah[m][0], ah[m][1], ah[m][2], ah[m][3], bh0[n], bh1[n]);
            #pragma unroll
            for (int m = 0; m < 2; m++)
                #pragma unroll
                for (int n = 0; n < 8; n++)
                    mma16816(c[m][n], al[m][0], al[m][1], al[m][2], al[m][3], bh0[n], bh1[n]);
            #pragma unroll
            for (int m = 0; m < 2; m++)
                #pragma unroll
                for (int n = 0; n < 8; n++)
                    mma16816(c[m][n], ah[m][0], ah[m][1], ah[m][2], ah[m][3], bl0[n], bl1[n]);
        }
        __syncthreads();
    }
    #undef G_STAGE

    // ---- epilogue ----
    if (MODE == 1 || blockIdx.z == 2) {
        #pragma unroll
        for (int m = 0; m < 2; m++) {
            float* cr = Cv + (size_t)(m0 + wm * 32 + m * 16 + g) * N + n0 + wn * 64 + 2 * tig;
            #pragma unroll
            for (int n = 0; n < 8; n++) {
                *(float2*)(cr + n * 8)         = make_float2(c[m][n][0], c[m][n][1]);
                *(float2*)(cr + 8 * N + n * 8) = make_float2(c[m][n][2], c[m][n][3]);
            }
        }
    } else {
        // fused RoPE + (scale) + hi/lo split for Q (z=0) or K (z=1)
        const bool isQ = (blockIdx.z == 0);
        unsigned* dh = (unsigned*)(isQ ? g_qh : g_kh);
        unsigned* dl = (unsigned*)(isQ ? g_ql : g_kl);
        const float sc = isQ ? 0.125f : 1.0f;
        #pragma unroll
        for (int m = 0; m < 2; m++) {
            int r0 = m0 + wm * 32 + m * 16 + g;
            float p0 = (float)pos[r0];
            float p1 = (float)pos[r0 + 8];
            #pragma unroll
            for (int n = 0; n < 8; n++) {
                int c0 = n0 + wn * 64 + n * 8 + 2 * tig;     // even column
                int i = (c0 & 63) >> 1;
                float inv = __expf(-(float)(2 * i) * (9.210340371976184f / 64.0f));
                float s0, cs0, s1, cs1;
                sincosf(p0 * inv, &s0, &cs0);
                sincosf(p1 * inv, &s1, &cs1);
                unsigned hh, ll;
                float e = c[m][n][0], o_ = c[m][n][1];
                split2((e * cs0 - o_ * s0) * sc, (e * s0 + o_ * cs0) * sc, hh, ll);
                size_t ix = ((size_t)r0 * D_MODEL + c0) >> 1;
                dh[ix] = hh; dl[ix] = ll;
                e = c[m][n][2]; o_ = c[m][n][3];
                split2((e * cs1 - o_ * s1) * sc, (e * s1 + o_ * cs1) * sc, hh, ll);
                ix = ((size_t)(r0 + 8) * D_MODEL + c0) >> 1;
                dh[ix] = hh; dl[ix] = ll;
            }
        }
    }
}

// ---------------------------------------------------------------------------
// V -> transposed per-(b,h) hi/lo bf16: vt[bh][d][s]
// ---------------------------------------------------------------------------
__global__ __launch_bounds__(256) void v_transpose_split_kernel(const float* __restrict__ v)
{
    __shared__ float T[32][33];
    const int tid = threadIdx.x;
    const int tx = tid & 31;
    const int ty = tid >> 5;
    const int s0 = blockIdx.x * 32;
    const int d0 = blockIdx.y * 32;
    const int bh = blockIdx.z;
    const int b  = bh >> 4;
    const int h  = bh & 15;

    #pragma unroll
    for (int i = 0; i < 4; i++) {
        int r = ty + i * 8;
        T[r][tx] = v[((size_t)(b * SEQ + s0 + r)) * D_MODEL + h * DK + d0 + tx];
    }
    __syncthreads();
    #pragma unroll
    for (int i = 0; i < 4; i++) {
        int dr = ty + i * 8;
        float x = T[tx][dr];
        __nv_bfloat16 hv = __float2bfloat16_rn(x);
        __nv_bfloat16 lv = __float2bfloat16_rn(x - __bfloat162float(hv));
        size_t off = ((size_t)(bh * DK + d0 + dr)) * SEQ + s0 + tx;
        g_vth[off] = hv;
        g_vtl[off] = lv;
    }
}

// ---------------------------------------------------------------------------
// Flash attention (mma.sync, ILP-ordered). Epilogue writes oh/ol directly.
// 128 threads = 4 warps; BR=64 queries (m16/warp), BC=64 keys.
// ---------------------------------------------------------------------------
#define FP 72

__global__ __launch_bounds__(128) void flash_mma_kernel()
{
    __shared__ __align__(16) __nv_bfloat16 Khs[64 * FP];
    __shared__ __align__(16) __nv_bfloat16 Kls[64 * FP];
    __shared__ __align__(16) __nv_bfloat16 Vhs[64 * FP];
    __shared__ __align__(16) __nv_bfloat16 Vls[64 * FP];

    const int bh = blockIdx.y;
    const int b  = bh >> 4;
    const int h  = bh & 15;
    const int qt = (int)gridDim.x - 1 - (int)blockIdx.x;   // long blocks first
    const int q0 = qt * 64;
    const int tid  = threadIdx.x;
    const int warp = tid >> 5;
    const int lane = tid & 31;
    const int g    = lane >> 2;
    const int tig  = lane & 3;
    const int wr0  = q0 + warp * 16;

    unsigned qh[4][4], ql[4][4];
    {
        const size_t r0 = ((size_t)(b * SEQ + wr0 + g)) * D_MODEL + h * DK;
        const size_t r1 = r0 + (size_t)8 * D_MODEL;
        #pragma unroll
        for (int kt = 0; kt < 4; kt++) {
            int d0 = kt * 16 + 2 * tig;
            qh[kt][0] = *(const unsigned*)&g_qh[r0 + d0];
            qh[kt][1] = *(const unsigned*)&g_qh[r1 + d0];
            qh[kt][2] = *(const unsigned*)&g_qh[r0 + d0 + 8];
            qh[kt][3] = *(const unsigned*)&g_qh[r1 + d0 + 8];
            ql[kt][0] = *(const unsigned*)&g_ql[r0 + d0];
            ql[kt][1] = *(const unsigned*)&g_ql[r1 + d0];
            ql[kt][2] = *(const unsigned*)&g_ql[r0 + d0 + 8];
            ql[kt][3] = *(const unsigned*)&g_ql[r1 + d0 + 8];
        }
    }

    float oa[8][4];
    #pragma unroll
    for (int nj = 0; nj < 8; nj++)
        #pragma unroll
        for (int e = 0; e < 4; e++) oa[nj][e] = 0.f;
    float m0 = -1e30f, m1 = -1e30f, l0 = 0.f, l1 = 0.f;

    const int kend = q0 + 64;
    for (int k0 = 0; k0 < kend; k0 += 64) {
        __syncthreads();
        #pragma unroll
        for (int i = 0; i < 4; i++) {
            int c  = tid + i * 128;
            int r  = c >> 3;
            int ch = c & 7;
            size_t ksrc = ((size_t)(b * SEQ + k0 + r)) * D_MODEL + h * DK + ch * 8;
            cpasync16(&Khs[r * FP + ch * 8], g_kh + ksrc);
            cpasync16(&Kls[r * FP + ch * 8], g_kl + ksrc);
            size_t vsrc = ((size_t)(bh * DK + r)) * SEQ + k0 + ch * 8;
            cpasync16(&Vhs[r * FP + ch * 8], g_vth + vsrc);
            cpasync16(&Vls[r * FP + ch * 8], g_vtl + vsrc);
        }
        CP_COMMIT();
        CP_WAIT(0);
        __syncthreads();

        float s[8][4];
        #pragma unroll
        for (int nj = 0; nj < 8; nj++)
            s[nj][0] = s[nj][1] = s[nj][2] = s[nj][3] = 0.f;
        #pragma unroll
        for (int kt = 0; kt < 4; kt++) {
            unsigned kb0[8], kb1[8], kc0[8], kc1[8];
            #pragma unroll
            for (int nj = 0; nj < 8; nj++) {
                int off = (nj * 8 + g) * FP + kt * 16 + 2 * tig;
                kb0[nj] = *(const unsigned*)&Khs[off];
                kb1[nj] = *(const unsigned*)&Khs[off + 8];
                kc0[nj] = *(const unsigned*)&Kls[off];
                kc1[nj] = *(const unsigned*)&Kls[off + 8];
            }
            #pragma unroll
            for (int nj = 0; nj < 8; nj++)
                mma16816(s[nj], qh[kt][0], qh[kt][1], qh[kt][2], qh[kt][3], kb0[nj], kb1[nj]);
            #pragma unroll
            for (int nj = 0; nj < 8; nj++)
                mma16816(s[nj], ql[kt][0], ql[kt][1], ql[kt][2], ql[kt][3], kb0[nj], kb1[nj]);
            #pragma unroll
            for (int nj = 0; nj < 8; nj++)
                mma16816(s[nj], qh[kt][0], qh[kt][1], qh[kt][2], qh[kt][3], kc0[nj], kc1[nj]);
        }

        if (k0 + 63 > wr0 + g) {
            int r0 = wr0 + g, r1 = r0 + 8;
            #pragma unroll
            for (int nj = 0; nj < 8; nj++) {
                int c = k0 + nj * 8 + 2 * tig;
                if (c     > r0) s[nj][0] = -1e30f;
                if (c + 1 > r0) s[nj][1] = -1e30f;
                if (c     > r1) s[nj][2] = -1e30f;
                if (c + 1 > r1) s[nj][3] = -1e30f;
            }
        }

        float rm0 = -1e30f, rm1 = -1e30f;
        #pragma unroll
        for (int nj = 0; nj < 8; nj++) {
            rm0 = fmaxf(rm0, fmaxf(s[nj][0], s[nj][1]));
            rm1 = fmaxf(rm1, fmaxf(s[nj][2], s[nj][3]));
        }
        rm0 = fmaxf(rm0, __shfl_xor_sync(0xffffffffu, rm0, 1));
        rm0 = fmaxf(rm0, __shfl_xor_sync(0xffffffffu, rm0, 2));
        rm1 = fmaxf(rm1, __shfl_xor_sync(0xffffffffu, rm1, 1));
        rm1 = fmaxf(rm1, __shfl_xor_sync(0xffffffffu, rm1, 2));

        float mn0 = fmaxf(m0, rm0), mn1 = fmaxf(m1, rm1);
        float corr0 = __expf(m0 - mn0), corr1 = __expf(m1 - mn1);
        float rs0 = 0.f, rs1 = 0.f;
        #pragma unroll
        for (int nj = 0; nj < 8; nj++) {
            s[nj][0] = __expf(s[nj][0] - mn0);
            s[nj][1] = __expf(s[nj][1] - mn0);
            s[nj][2] = __expf(s[nj][2] - mn1);
            s[nj][3] = __expf(s[nj][3] - mn1);
            rs0 += s[nj][0] + s[nj][1];
            rs1 += s[nj][2] + s[nj][3];
        }
        rs0 += __shfl_xor_sync(0xffffffffu, rs0, 1);
        rs0 += __shfl_xor_sync(0xffffffffu, rs0, 2);
        rs1 += __shfl_xor_sync(0xffffffffu, rs1, 1);
        rs1 += __shfl_xor_sync(0xffffffffu, rs1, 2);
        l0 = l0 * corr0 + rs0;
        l1 = l1 * corr1 + rs1;
        m0 = mn0; m1 = mn1;

        #pragma unroll
        for (int nj = 0; nj < 8; nj++) {
            oa[nj][0] *= corr0; oa[nj][1] *= corr0;
            oa[nj][2] *= corr1; oa[nj][3] *= corr1;
        }

        unsigned pah[4][4], pal[4][4];
        #pragma unroll
        for (int kt = 0; kt < 4; kt++) {
            split2(s[2*kt][0],   s[2*kt][1],   pah[kt][0], pal[kt][0]);
            split2(s[2*kt][2],   s[2*kt][3],   pah[kt][1], pal[kt][1]);
            split2(s[2*kt+1][0], s[2*kt+1][1], pah[kt][2], pal[kt][2]);
            split2(s[2*kt+1][2], s[2*kt+1][3], pah[kt][3], pal[kt][3]);
        }

        #pragma unroll
        for (int kt = 0; kt < 4; kt++) {
            unsigned vb0[8], vb1[8], vc0[8], vc1[8];
            #pragma unroll
            for (int nj = 0; nj < 8; nj++) {
                int off = (nj * 8 + g) * FP + kt * 16 + 2 * tig;
                vb0[nj] = *(const unsigned*)&Vhs[off];
                vb1[nj] = *(const unsigned*)&Vhs[off + 8];
                vc0[nj] = *(const unsigned*)&Vls[off];
                vc1[nj] = *(const unsigned*)&Vls[off + 8];
            }
            #pragma unroll
            for (int nj = 0; nj < 8; nj++)
                mma16816(oa[nj], pah[kt][0], pah[kt][1], pah[kt][2], pah[kt][3], vb0[nj], vb1[nj]);
            #pragma unroll
            for (int nj = 0; nj < 8; nj++)
                mma16816(oa[nj], pal[kt][0], pal[kt][1], pal[kt][2], pal[kt][3], vb0[nj], vb1[nj]);
            #pragma unroll
            for (int nj = 0; nj < 8; nj++)
                mma16816(oa[nj], pah[kt][0], pah[kt][1], pah[kt][2], pah[kt][3], vc0[nj], vc1[nj]);
        }
    }

    // ---- epilogue: normalize and write hi/lo bf16 splits of O ----
    {
        float inv0 = 1.0f / l0, inv1 = 1.0f / l1;
        unsigned* dh = (unsigned*)g_oh;
        unsigned* dl = (unsigned*)g_ol;
        const size_t row0 = (size_t)(b * SEQ + wr0 + g);
        #pragma unroll
        for (int nj = 0; nj < 8; nj++) {
            int d = h * DK + nj * 8 + 2 * tig;       // even
            unsigned hh, ll;
            split2(oa[nj][0] * inv0, oa[nj][1] * inv0, hh, ll);
            size_t ix = (row0 * D_MODEL + d) >> 1;
            dh[ix] = hh; dl[ix] = ll;
            split2(oa[nj][2] * inv1, oa[nj][3] * inv1, hh, ll);
            ix = ((row0 + 8) * D_MODEL + d) >> 1;
            dh[ix] = hh; dl[ix] = ll;
        }
    }
}

// ---------------------------------------------------------------------------
// Launch
// ---------------------------------------------------------------------------
extern "C" void kernel_launch(void* const* d_in, const int* in_sizes, int n_in,
                              void* d_out, int out_size)
{
    const float* x  = (const float*)d_in[0];
    const float* Wq = (const float*)d_in[1];
    const float* Wk = (const float*)d_in[2];
    const float* Wv = (const float*)d_in[3];
    const float* Wo = (const float*)d_in[4];
    const int*   tp = (const int*)d_in[5];
    float* out = (float*)d_out;

    float* vp;
    cudaGetSymbolAddress((void**)&vp, g_v);
    __nv_bfloat16 *xh, *xl, *wh, *wl, *oh, *ol;
    cudaGetSymbolAddress((void**)&xh, g_xh);
    cudaGetSymbolAddress((void**)&xl, g_xl);
    cudaGetSymbolAddress((void**)&wh, g_wh);
    cudaGetSymbolAddress((void**)&wl, g_wl);
    cudaGetSymbolAddress((void**)&oh, g_oh);
    cudaGetSymbolAddress((void**)&ol, g_ol);

    cudaFuncSetAttribute(gemm_mma<0>, cudaFuncAttributeMaxDynamicSharedMemorySize, G3_SMEM);
    cudaFuncSetAttribute(gemm_mma<1>, cudaFuncAttributeMaxDynamicSharedMemorySize, G3_SMEM);

    const size_t WSTRIDE = (size_t)D_MODEL * D_MODEL;

    // 1) split inputs to bf16 hi/lo (4 pairs/thread)
    split_kernel<<<(NPAIRS / 4 + 255) / 256, 256>>>(x,  xh, xl, NPAIRS);
    split_kernel<<<(WPAIRS / 4 + 255) / 256, 256>>>(Wq, wh + 0 * WSTRIDE, wl + 0 * WSTRIDE, WPAIRS);
    split_kernel<<<(WPAIRS / 4 + 255) / 256, 256>>>(Wk, wh + 1 * WSTRIDE, wl + 1 * WSTRIDE, WPAIRS);
    split_kernel<<<(WPAIRS / 4 + 255) / 256, 256>>>(Wv, wh + 2 * WSTRIDE, wl + 2 * WSTRIDE, WPAIRS);
    split_kernel<<<(WPAIRS / 4 + 255) / 256, 256>>>(Wo, wh + 3 * WSTRIDE, wl + 3 * WSTRIDE, WPAIRS);

    // 2) QKV projections with fused RoPE + split epilogue
    dim3 gq(D_MODEL / 256, M_TOT / 128, 3);
    gemm_mma<0><<<gq, 512, G3_SMEM>>>(xh, xl,
        wh + 0 * WSTRIDE, wl + 0 * WSTRIDE,
        wh + 1 * WSTRIDE, wl + 1 * WSTRIDE,
        wh + 2 * WSTRIDE, wl + 2 * WSTRIDE,
        vp, tp, M_TOT, D_MODEL, D_MODEL);

    // 3) V transpose + split
    v_transpose_split_kernel<<<dim3(SEQ / 32, DK / 32, BATCH * NHEAD), 256>>>(vp);

    // 4) causal flash attention (writes oh/ol directly)
    flash_mma_kernel<<<dim3(SEQ / 64, BATCH * NHEAD), 128>>>();

    // 5) output projection
    dim3 go(D_MODEL / 256, M_TOT / 128, 1);
    gemm_mma<1><<<go, 512, G3_SMEM>>>(oh, ol,
        wh + 3 * WSTRIDE, wl + 3 * WSTRIDE,
        wh + 3 * WSTRIDE, wl + 3 * WSTRIDE,
        wh + 3 * WSTRIDE, wl + 3 * WSTRIDE,
        out, tp, M_TOT, D_MODEL, D_MODEL);
}

// round 17
// speedup vs baseline: 5.0678x; 1.0224x over previous
#include <cuda_runtime.h>
#include <cuda_bf16.h>
#include <cstdint>

#define D_MODEL 1024
#define NHEAD   16
#define DK      64
#define BATCH   2
#define SEQ     2048
#define M_TOT   (BATCH*SEQ)   // 4096
#define NPAIRS  (M_TOT*D_MODEL/2)
#define WPAIRS  (D_MODEL*D_MODEL/2)

// bf16 hi/lo splits (allocation-free rule: __device__ globals)
__device__ __nv_bfloat16 g_xh[(size_t)M_TOT*D_MODEL];
__device__ __nv_bfloat16 g_xl[(size_t)M_TOT*D_MODEL];
__device__ __nv_bfloat16 g_wh[(size_t)4*D_MODEL*D_MODEL];
__device__ __nv_bfloat16 g_wl[(size_t)4*D_MODEL*D_MODEL];
__device__ __nv_bfloat16 g_oh[(size_t)M_TOT*D_MODEL];
__device__ __nv_bfloat16 g_ol[(size_t)M_TOT*D_MODEL];
__device__ __nv_bfloat16 g_qh[(size_t)M_TOT*D_MODEL];
__device__ __nv_bfloat16 g_ql[(size_t)M_TOT*D_MODEL];
__device__ __nv_bfloat16 g_kh[(size_t)M_TOT*D_MODEL];
__device__ __nv_bfloat16 g_kl[(size_t)M_TOT*D_MODEL];
__device__ __nv_bfloat16 g_vth[(size_t)M_TOT*D_MODEL];   // V^T per (b,h): [bh][dim][seq]
__device__ __nv_bfloat16 g_vtl[(size_t)M_TOT*D_MODEL];

// ---------------------------------------------------------------------------
// common helpers
// ---------------------------------------------------------------------------
__device__ __forceinline__ void split2(float x, float y, unsigned& h, unsigned& l)
{
    __nv_bfloat162 hh = __floats2bfloat162_rn(x, y);
    float rx = x - __bfloat162float(hh.x);
    float ry = y - __bfloat162float(hh.y);
    __nv_bfloat162 ll = __floats2bfloat162_rn(rx, ry);
    h = *reinterpret_cast<unsigned*>(&hh);
    l = *reinterpret_cast<unsigned*>(&ll);
}

__device__ __forceinline__ void mma16816(float* c,
    unsigned a0, unsigned a1, unsigned a2, unsigned a3,
    unsigned b0, unsigned b1)
{
    asm volatile(
        "mma.sync.aligned.m16n8k16.row.col.f32.bf16.bf16.f32 "
        "{%0,%1,%2,%3},{%4,%5,%6,%7},{%8,%9},{%0,%1,%2,%3};\n"
        : "+f"(c[0]), "+f"(c[1]), "+f"(c[2]), "+f"(c[3])
        : "r"(a0), "r"(a1), "r"(a2), "r"(a3), "r"(b0), "r"(b1));
}

__device__ __forceinline__ uint32_t smem_u32(const void* p) {
    uint32_t a;
    asm("{ .reg .u64 t; cvta.to.shared.u64 t, %1; cvt.u32.u64 %0, t; }"
        : "=r"(a) : "l"(p));
    return a;
}
__device__ __forceinline__ void cp16r(uint32_t saddr, const void* gsrc)
{
    asm volatile("cp.async.cg.shared.global [%0], [%1], 16;\n" :: "r"(saddr), "l"(gsrc));
}
__device__ __forceinline__ void cpasync16(void* smem_dst, const void* gsrc)
{
    unsigned s = (unsigned)__cvta_generic_to_shared(smem_dst);
    asm volatile("cp.async.cg.shared.global [%0], [%1], 16;\n" :: "r"(s), "l"(gsrc));
}
#define CP_COMMIT() asm volatile("cp.async.commit_group;\n" ::: "memory")
#define CP_WAIT(n)  asm volatile("cp.async.wait_group %0;\n" :: "n"(n) : "memory")

// ---------------------------------------------------------------------------
// ONE split kernel for x + all 4 weights (region-mapped by blockIdx)
// 4 pairs per thread (float4 in, uint4 out)
// ---------------------------------------------------------------------------
#define XBLKS (NPAIRS/4/256)     // 2048
#define WBLKS (WPAIRS/4/256)     // 512

__global__ void split_all_kernel(const float* __restrict__ x,
                                 const float* __restrict__ Wq,
                                 const float* __restrict__ Wk,
                                 const float* __restrict__ Wv,
                                 const float* __restrict__ Wo)
{
    const size_t WS = (size_t)D_MODEL * D_MODEL;
    int blk = blockIdx.x;
    const float* src; __nv_bfloat16 *h, *l; int rel;
    if (blk < XBLKS)                 { src = x;  h = g_xh;          l = g_xl;          rel = blk; }
    else if (blk < XBLKS + WBLKS)    { src = Wq; h = g_wh;          l = g_wl;          rel = blk - XBLKS; }
    else if (blk < XBLKS + 2*WBLKS)  { src = Wk; h = g_wh + WS;     l = g_wl + WS;     rel = blk - XBLKS - WBLKS; }
    else if (blk < XBLKS + 3*WBLKS)  { src = Wv; h = g_wh + 2*WS;   l = g_wl + 2*WS;   rel = blk - XBLKS - 2*WBLKS; }
    else                             { src = Wo; h = g_wh + 3*WS;   l = g_wl + 3*WS;   rel = blk - XBLKS - 3*WBLKS; }

    int p0 = (rel * 256 + threadIdx.x) * 4;     // first pair index within region
    float4 a = ((const float4*)src)[p0 >> 1];
    float4 b = ((const float4*)src)[(p0 >> 1) + 1];
    uint4 hh, ll;
    split2(a.x, a.y, hh.x, ll.x);
    split2(a.z, a.w, hh.y, ll.y);
    split2(b.x, b.y, hh.z, ll.z);
    split2(b.z, b.w, hh.w, ll.w);
    ((uint4*)h)[p0 >> 2] = hh;
    ((uint4*)l)[p0 >> 2] = ll;
}

// ---------------------------------------------------------------------------
// GEMM via mma.sync split-bf16: C[M,N] = A[M,K] * B[N,K]^T.
// 128x256 block tile, 512 threads = 16 warps (4m x 4n), each warp m32 x n64.
// BK=32 chunks, THREE-stage cp.async pipeline (184KB smem, prefetch dist 2).
// MODE 0 epilogues: z=0 RoPE+scale+split->qh/ql; z=1 RoPE+split->kh/kl;
//                   z=2 smem-transpose + split -> g_vth/g_vtl (V^T).
// MODE 1: plain fp32 writeback to Cv.
// ---------------------------------------------------------------------------
#define GP2     40                        // bf16 pitch (80B rows)
#define A3_ARR  10240                     // bytes: 128 rows * 80
#define B3_ARR  20480                     // bytes: 256 rows * 80
#define G3_BUF  (2*A3_ARR + 2*B3_ARR)     // 61440 per buffer
#define G3_SMEM (3*G3_BUF)                // 184320 (3-stage)
#define VT_P    136                       // V^T transpose smem pitch (s + 8)

template<int MODE>
__global__ __launch_bounds__(512) void gemm_mma(
    const __nv_bfloat16* __restrict__ Ah, const __nv_bfloat16* __restrict__ Al,
    const __nv_bfloat16* Bh0, const __nv_bfloat16* Bl0,
    const __nv_bfloat16* Bh1, const __nv_bfloat16* Bl1,
    const __nv_bfloat16* Bh2, const __nv_bfloat16* Bl2,
    float* Cv, const int* __restrict__ pos,
    int M, int N, int K)
{
    extern __shared__ __align__(16) char gsm[];
    const __nv_bfloat16 *Bh, *Bl;
    if (blockIdx.z == 0)      { Bh = Bh0; Bl = Bl0; }
    else if (blockIdx.z == 1) { Bh = Bh1; Bl = Bl1; }
    else                      { Bh = Bh2; Bl = Bl2; }

    const uint32_t sb = smem_u32(gsm);
    const __nv_bfloat16* sm = (const __nv_bfloat16*)gsm;

    const int m0 = blockIdx.y * 128;
    const int n0 = blockIdx.x * 256;
    const int tid  = threadIdx.x;
    const int warp = tid >> 5;
    const int lane = tid & 31;
    const int g    = lane >> 2;
    const int tig  = lane & 3;
    const int wm   = warp >> 2;           // 0..3 -> m offset 32*wm
    const int wn   = warp & 3;            // 0..3 -> n offset 64*wn
    const int nk   = K >> 5;              // chunks of 32

    float c[2][8][4];
    #pragma unroll
    for (int m = 0; m < 2; m++)
        #pragma unroll
        for (int n = 0; n < 8; n++)
            c[m][n][0] = c[m][n][1] = c[m][n][2] = c[m][n][3] = 0.f;

    #define G_STAGE(kc, bi) do {                                               \
        uint32_t bb = sb + (bi) * G3_BUF;                                      \
        {                                                                      \
            int r = tid >> 2, ch = tid & 3;                                    \
            uint32_t d = r * 80 + ch * 16;                                     \
            size_t as = (size_t)(m0 + r) * K + (kc) * 32 + ch * 8;             \
            cp16r(bb + d,          Ah + as);                                   \
            cp16r(bb + A3_ARR + d, Al + as);                                   \
        }                                                                      \
        _Pragma("unroll")                                                      \
        for (int i = 0; i < 2; i++) {                                          \
            int idx = tid + i * 512;                                           \
            int r = idx >> 2, ch = idx & 3;                                    \
            uint32_t d = r * 80 + ch * 16;                                     \
            size_t bs = (size_t)(n0 + r) * K + (kc) * 32 + ch * 8;             \
            cp16r(bb + 2*A3_ARR + d,          Bh + bs);                        \
            cp16r(bb + 2*A3_ARR + B3_ARR + d, Bl + bs);                        \
        }                                                                      \
        CP_COMMIT();                                                           \
    } while (0)

    G_STAGE(0, 0);
    G_STAGE(1, 1);

    for (int kc = 0; kc < nk; kc++) {
        if (kc + 2 < nk)      { G_STAGE(kc + 2, (kc + 2) % 3); CP_WAIT(2); }
        else if (kc + 1 < nk) { CP_WAIT(1); }
        else                  { CP_WAIT(0); }
        __syncthreads();

        const __nv_bfloat16* sAh = sm + (kc % 3) * (G3_BUF / 2);
        const __nv_bfloat16* sAl = sAh + A3_ARR / 2;
        const __nv_bfloat16* sBh = sAh + A3_ARR;             // 2*A3_ARR bytes in
        const __nv_bfloat16* sBl = sBh + B3_ARR / 2;

        #pragma unroll
        for (int kt = 0; kt < 2; kt++) {
            const int cb = kt * 16 + 2 * tig;
            unsigned ah[2][4], al[2][4];
            #pragma unroll
            for (int m = 0; m < 2; m++) {
                int rw = wm * 32 + m * 16;
                ah[m][0] = *(const unsigned*)&sAh[(rw + g)     * GP2 + cb];
                ah[m][1] = *(const unsigned*)&sAh[(rw + g + 8) * GP2 + cb];
                ah[m][2] = *(const unsigned*)&sAh[(rw + g)     * GP2 + cb + 8];
                ah[m][3] = *(const unsigned*)&sAh[(rw + g + 8) * GP2 + cb + 8];
                al[m][0] = *(const unsigned*)&sAl[(rw + g)     * GP2 + cb];
                al[m][1] = *(const unsigned*)&sAl[(rw + g + 8) * GP2 + cb];
                al[m][2] = *(const unsigned*)&sAl[(rw + g)     * GP2 + cb + 8];
                al[m][3] = *(const unsigned*)&sAl[(rw + g + 8) * GP2 + cb + 8];
            }
            unsigned bh0[8], bh1[8], bl0[8], bl1[8];
            #pragma unroll
            for (int n = 0; n < 8; n++) {
                int off = (wn * 64 + n * 8 + g) * GP2 + cb;
                bh0[n] = *(const unsigned*)&sBh[off];
                bh1[n] = *(const unsigned*)&sBh[off + 8];
                bl0[n] = *(const unsigned*)&sBl[off];
                bl1[n] = *(const unsigned*)&sBl[off + 8];
            }
            #pragma unroll
            for (int m = 0; m < 2; m++)
                #pragma unroll
                for (int n = 0; n < 8; n++)
                    mma16816(c[m][n], ah[m][0], ah[m][1], ah[m][2], ah[m][3], bh0[n], bh1[n]);
            #pragma unroll
            for (int m = 0; m < 2; m++)
                #pragma unroll
                for (int n = 0; n < 8; n++)
                    mma16816(c[m][n], al[m][0], al[m][1], al[m][2], al[m][3], bh0[n], bh1[n]);
            #pragma unroll
            for (int m = 0; m < 2; m++)
                #pragma unroll
                for (int n = 0; n < 8; n++)
                    mma16816(c[m][n], ah[m][0], ah[m][1], ah[m][2], ah[m][3], bl0[n], bl1[n]);
        }
        __syncthreads();
    }
    #undef G_STAGE

    // ---- epilogues ----
    if (MODE == 0 && blockIdx.z == 2) {
        // V: transpose in (now free) pipeline smem, split, write V^T hi/lo.
        __nv_bfloat16* tH = (__nv_bfloat16*)gsm;            // [256][VT_P]
        __nv_bfloat16* tL = tH + 256 * VT_P;
        #pragma unroll
        for (int m = 0; m < 2; m++) {
            int sr = wm * 32 + m * 16 + g;                  // local seq row
            #pragma unroll
            for (int n = 0; n < 8; n++) {
                int cc = wn * 64 + n * 8 + 2 * tig;         // local dim col
                #pragma unroll
                for (int e = 0; e < 4; e++) {
                    float v = c[m][n][e];
                    int col = cc + (e & 1);
                    int row = sr + (e >> 1) * 8;
                    __nv_bfloat16 hv = __float2bfloat16_rn(v);
                    __nv_bfloat16 lv = __float2bfloat16_rn(v - __bfloat162float(hv));
                    tH[col * VT_P + row] = hv;
                    tL[col * VT_P + row] = lv;
                }
            }
        }
        __syncthreads();
        const int b  = m0 >> 11;
        const int s0 = m0 & 2047;
        for (int rr = warp; rr < 256; rr += 16) {
            int col = n0 + rr;
            int hh  = col >> 6;
            int dd  = col & 63;
            size_t go = ((size_t)((b * 16 + hh) * 64 + dd)) * SEQ + s0;
            unsigned u0 = *(const unsigned*)&tH[rr * VT_P + lane * 2];
            unsigned u1 = *(const unsigned*)&tH[rr * VT_P + 64 + lane * 2];
            ((unsigned*)(g_vth + go))[lane]      = u0;
            ((unsigned*)(g_vth + go))[lane + 32] = u1;
            u0 = *(const unsigned*)&tL[rr * VT_P + lane * 2];
            u1 = *(const unsigned*)&tL[rr * VT_P + 64 + lane * 2];
            ((unsigned*)(g_vtl + go))[lane]      = u0;
            ((unsigned*)(g_vtl + go))[lane + 32] = u1;
        }
    } else if (MODE == 1) {
        #pragma unroll
        for (int m = 0; m < 2; m++) {
            float* cr = Cv + (size_t)(m0 + wm * 32 + m * 16 + g) * N + n0 + wn * 64 + 2 * tig;
            #pragma unroll
            for (int n = 0; n < 8; n++) {
                *(float2*)(cr + n * 8)         = make_float2(c[m][n][0], c[m][n][1]);
                *(float2*)(cr + 8 * N + n * 8) = make_float2(c[m][n][2], c[m][n][3]);
            }
        }
    } else {
        // fused RoPE + (scale) + hi/lo split for Q (z=0) or K (z=1)
        const bool isQ = (blockIdx.z == 0);
        unsigned* dh = (unsigned*)(isQ ? g_qh : g_kh);
        unsigned* dl = (unsigned*)(isQ ? g_ql : g_kl);
        const float sc = isQ ? 0.125f : 1.0f;
        #pragma unroll
        for (int m = 0; m < 2; m++) {
            int r0 = m0 + wm * 32 + m * 16 + g;
            float p0 = (float)pos[r0];
            float p1 = (float)pos[r0 + 8];
            #pragma unroll
            for (int n = 0; n < 8; n++) {
                int c0 = n0 + wn * 64 + n * 8 + 2 * tig;     // even column
                int i = (c0 & 63) >> 1;
                float inv = __expf(-(float)(2 * i) * (9.210340371976184f / 64.0f));
                float s0, cs0, s1, cs1;
                sincosf(p0 * inv, &s0, &cs0);
                sincosf(p1 * inv, &s1, &cs1);
                unsigned hh, ll;
                float e = c[m][n][0], o_ = c[m][n][1];
                split2((e * cs0 - o_ * s0) * sc, (e * s0 + o_ * cs0) * sc, hh, ll);
                size_t ix = ((size_t)r0 * D_MODEL + c0) >> 1;
                dh[ix] = hh; dl[ix] = ll;
                e = c[m][n][2]; o_ = c[m][n][3];
                split2((e * cs1 - o_ * s1) * sc, (e * s1 + o_ * cs1) * sc, hh, ll);
                ix = ((size_t)(r0 + 8) * D_MODEL + c0) >> 1;
                dh[ix] = hh; dl[ix] = ll;
            }
        }
    }
}

// ---------------------------------------------------------------------------
// Flash attention (mma.sync, ILP-ordered). Epilogue writes oh/ol directly.
// 128 threads = 4 warps; BR=64 queries (m16/warp), BC=64 keys.
// ---------------------------------------------------------------------------
#define FP 72

__global__ __launch_bounds__(128) void flash_mma_kernel()
{
    __shared__ __align__(16) __nv_bfloat16 Khs[64 * FP];
    __shared__ __align__(16) __nv_bfloat16 Kls[64 * FP];
    __shared__ __align__(16) __nv_bfloat16 Vhs[64 * FP];
    __shared__ __align__(16) __nv_bfloat16 Vls[64 * FP];

    const int bh = blockIdx.y;
    const int b  = bh >> 4;
    const int h  = bh & 15;
    const int qt = (int)gridDim.x - 1 - (int)blockIdx.x;   // long blocks first
    const int q0 = qt * 64;
    const int tid  = threadIdx.x;
    const int warp = tid >> 5;
    const int lane = tid & 31;
    const int g    = lane >> 2;
    const int tig  = lane & 3;
    const int wr0  = q0 + warp * 16;

    unsigned qh[4][4], ql[4][4];
    {
        const size_t r0 = ((size_t)(b * SEQ + wr0 + g)) * D_MODEL + h * DK;
        const size_t r1 = r0 + (size_t)8 * D_MODEL;
        #pragma unroll
        for (int kt = 0; kt < 4; kt++) {
            int d0 = kt * 16 + 2 * tig;
            qh[kt][0] = *(const unsigned*)&g_qh[r0 + d0];
            qh[kt][1] = *(const unsigned*)&g_qh[r1 + d0];
            qh[kt][2] = *(const unsigned*)&g_qh[r0 + d0 + 8];
            qh[kt][3] = *(const unsigned*)&g_qh[r1 + d0 + 8];
            ql[kt][0] = *(const unsigned*)&g_ql[r0 + d0];
            ql[kt][1] = *(const unsigned*)&g_ql[r1 + d0];
            ql[kt][2] = *(const unsigned*)&g_ql[r0 + d0 + 8];
            ql[kt][3] = *(const unsigned*)&g_ql[r1 + d0 + 8];
        }
    }

    float oa[8][4];
    #pragma unroll
    for (int nj = 0; nj < 8; nj++)
        #pragma unroll
        for (int e = 0; e < 4; e++) oa[nj][e] = 0.f;
    float m0 = -1e30f, m1 = -1e30f, l0 = 0.f, l1 = 0.f;

    const int kend = q0 + 64;
    for (int k0 = 0; k0 < kend; k0 += 64) {
        __syncthreads();
        #pragma unroll
        for (int i = 0; i < 4; i++) {
            int c  = tid + i * 128;
            int r  = c >> 3;
            int ch = c & 7;
            size_t ksrc = ((size_t)(b * SEQ + k0 + r)) * D_MODEL + h * DK + ch * 8;
            cpasync16(&Khs[r * FP + ch * 8], g_kh + ksrc);
            cpasync16(&Kls[r * FP + ch * 8], g_kl + ksrc);
            size_t vsrc = ((size_t)(bh * DK + r)) * SEQ + k0 + ch * 8;
            cpasync16(&Vhs[r * FP + ch * 8], g_vth + vsrc);
            cpasync16(&Vls[r * FP + ch * 8], g_vtl + vsrc);
        }
        CP_COMMIT();
        CP_WAIT(0);
        __syncthreads();

        float s[8][4];
        #pragma unroll
        for (int nj = 0; nj < 8; nj++)
            s[nj][0] = s[nj][1] = s[nj][2] = s[nj][3] = 0.f;
        #pragma unroll
        for (int kt = 0; kt < 4; kt++) {
            unsigned kb0[8], kb1[8], kc0[8], kc1[8];
            #pragma unroll
            for (int nj = 0; nj < 8; nj++) {
                int off = (nj * 8 + g) * FP + kt * 16 + 2 * tig;
                kb0[nj] = *(const unsigned*)&Khs[off];
                kb1[nj] = *(const unsigned*)&Khs[off + 8];
                kc0[nj] = *(const unsigned*)&Kls[off];
                kc1[nj] = *(const unsigned*)&Kls[off + 8];
            }
            #pragma unroll
            for (int nj = 0; nj < 8; nj++)
                mma16816(s[nj], qh[kt][0], qh[kt][1], qh[kt][2], qh[kt][3], kb0[nj], kb1[nj]);
            #pragma unroll
            for (int nj = 0; nj < 8; nj++)
                mma16816(s[nj], ql[kt][0], ql[kt][1], ql[kt][2], ql[kt][3], kb0[nj], kb1[nj]);
            #pragma unroll
            for (int nj = 0; nj < 8; nj++)
                mma16816(s[nj], qh[kt][0], qh[kt][1], qh[kt][2], qh[kt][3], kc0[nj], kc1[nj]);
        }

        if (k0 + 63 > wr0 + g) {
            int r0 = wr0 + g, r1 = r0 + 8;
            #pragma unroll
            for (int nj = 0; nj < 8; nj++) {
                int c = k0 + nj * 8 + 2 * tig;
                if (c     > r0) s[nj][0] = -1e30f;
                if (c + 1 > r0) s[nj][1] = -1e30f;
                if (c     > r1) s[nj][2] = -1e30f;
                if (c + 1 > r1) s[nj][3] = -1e30f;
            }
        }

        float rm0 = -1e30f, rm1 = -1e30f;
        #pragma unroll
        for (int nj = 0; nj < 8; nj++) {
            rm0 = fmaxf(rm0, fmaxf(s[nj][0], s[nj][1]));
            rm1 = fmaxf(rm1, fmaxf(s[nj][2], s[nj][3]));
        }
        rm0 = fmaxf(rm0, __shfl_xor_sync(0xffffffffu, rm0, 1));
        rm0 = fmaxf(rm0, __shfl_xor_sync(0xffffffffu, rm0, 2));
        rm1 = fmaxf(rm1, __shfl_xor_sync(0xffffffffu, rm1, 1));
        rm1 = fmaxf(rm1, __shfl_xor_sync(0xffffffffu, rm1, 2));

        float mn0 = fmaxf(m0, rm0), mn1 = fmaxf(m1, rm1);
        float corr0 = __expf(m0 - mn0), corr1 = __expf(m1 - mn1);
        float rs0 = 0.f, rs1 = 0.f;
        #pragma unroll
        for (int nj = 0; nj < 8; nj++) {
            s[nj][0] = __expf(s[nj][0] - mn0);
            s[nj][1] = __expf(s[nj][1] - mn0);
            s[nj][2] = __expf(s[nj][2] - mn1);
            s[nj][3] = __expf(s[nj][3] - mn1);
            rs0 += s[nj][0] + s[nj][1];
            rs1 += s[nj][2] + s[nj][3];
        }
        rs0 += __shfl_xor_sync(0xffffffffu, rs0, 1);
        rs0 += __shfl_xor_sync(0xffffffffu, rs0, 2);
        rs1 += __shfl_xor_sync(0xffffffffu, rs1, 1);
        rs1 += __shfl_xor_sync(0xffffffffu, rs1, 2);
        l0 = l0 * corr0 + rs0;
        l1 = l1 * corr1 + rs1;
        m0 = mn0; m1 = mn1;

        #pragma unroll
        for (int nj = 0; nj < 8; nj++) {
            oa[nj][0] *= corr0; oa[nj][1] *= corr0;
            oa[nj][2] *= corr1; oa[nj][3] *= corr1;
        }

        unsigned pah[4][4], pal[4][4];
        #pragma unroll
        for (int kt = 0; kt < 4; kt++) {
            split2(s[2*kt][0],   s[2*kt][1],   pah[kt][0], pal[kt][0]);
            split2(s[2*kt][2],   s[2*kt][3],   pah[kt][1], pal[kt][1]);
            split2(s[2*kt+1][0], s[2*kt+1][1], pah[kt][2], pal[kt][2]);
            split2(s[2*kt+1][2], s[2*kt+1][3], pah[kt][3], pal[kt][3]);
        }

        #pragma unroll
        for (int kt = 0; kt < 4; kt++) {
            unsigned vb0[8], vb1[8], vc0[8], vc1[8];
            #pragma unroll
            for (int nj = 0; nj < 8; nj++) {
                int off = (nj * 8 + g) * FP + kt * 16 + 2 * tig;
                vb0[nj] = *(const unsigned*)&Vhs[off];
                vb1[nj] = *(const unsigned*)&Vhs[off + 8];
                vc0[nj] = *(const unsigned*)&Vls[off];
                vc1[nj] = *(const unsigned*)&Vls[off + 8];
            }
            #pragma unroll
            for (int nj = 0; nj < 8; nj++)
                mma16816(oa[nj], pah[kt][0], pah[kt][1], pah[kt][2], pah[kt][3], vb0[nj], vb1[nj]);
            #pragma unroll
            for (int nj = 0; nj < 8; nj++)
                mma16816(oa[nj], pal[kt][0], pal[kt][1], pal[kt][2], pal[kt][3], vb0[nj], vb1[nj]);
            #pragma unroll
            for (int nj = 0; nj < 8; nj++)
                mma16816(oa[nj], pah[kt][0], pah[kt][1], pah[kt][2], pah[kt][3], vc0[nj], vc1[nj]);
        }
    }

    // ---- epilogue: normalize and write hi/lo bf16 splits of O ----
    {
        float inv0 = 1.0f / l0, inv1 = 1.0f / l1;
        unsigned* dh = (unsigned*)g_oh;
        unsigned* dl = (unsigned*)g_ol;
        const size_t row0 = (size_t)(b * SEQ + wr0 + g);
        #pragma unroll
        for (int nj = 0; nj < 8; nj++) {
            int d = h * DK + nj * 8 + 2 * tig;       // even
            unsigned hh, ll;
            split2(oa[nj][0] * inv0, oa[nj][1] * inv0, hh, ll);
            size_t ix = (row0 * D_MODEL + d) >> 1;
            dh[ix] = hh; dl[ix] = ll;
            split2(oa[nj][2] * inv1, oa[nj][3] * inv1, hh, ll);
            ix = ((row0 + 8) * D_MODEL + d) >> 1;
            dh[ix] = hh; dl[ix] = ll;
        }
    }
}

// ---------------------------------------------------------------------------
// Launch (4 kernels total)
// ---------------------------------------------------------------------------
extern "C" void kernel_launch(void* const* d_in, const int* in_sizes, int n_in,
                              void* d_out, int out_size)
{
    const float* x  = (const float*)d_in[0];
    const float* Wq = (const float*)d_in[1];
    const float* Wk = (const float*)d_in[2];
    const float* Wv = (const float*)d_in[3];
    const float* Wo = (const float*)d_in[4];
    const int*   tp = (const int*)d_in[5];
    float* out = (float*)d_out;

    __nv_bfloat16 *xh, *xl, *wh, *wl, *oh, *ol;
    cudaGetSymbolAddress((void**)&xh, g_xh);
    cudaGetSymbolAddress((void**)&xl, g_xl);
    cudaGetSymbolAddress((void**)&wh, g_wh);
    cudaGetSymbolAddress((void**)&wl, g_wl);
    cudaGetSymbolAddress((void**)&oh, g_oh);
    cudaGetSymbolAddress((void**)&ol, g_ol);

    cudaFuncSetAttribute(gemm_mma<0>, cudaFuncAttributeMaxDynamicSharedMemorySize, G3_SMEM);
    cudaFuncSetAttribute(gemm_mma<1>, cudaFuncAttributeMaxDynamicSharedMemorySize, G3_SMEM);

    const size_t WSTRIDE = (size_t)D_MODEL * D_MODEL;

    // 1) split x + all weights (one launch)
    split_all_kernel<<<XBLKS + 4 * WBLKS, 256>>>(x, Wq, Wk, Wv, Wo);

    // 2) QKV projections with fused RoPE/split + V^T epilogues
    dim3 gq(D_MODEL / 256, M_TOT / 128, 3);
    gemm_mma<0><<<gq, 512, G3_SMEM>>>(xh, xl,
        wh + 0 * WSTRIDE, wl + 0 * WSTRIDE,
        wh + 1 * WSTRIDE, wl + 1 * WSTRIDE,
        wh + 2 * WSTRIDE, wl + 2 * WSTRIDE,
        out, tp, M_TOT, D_MODEL, D_MODEL);

    // 3) causal flash attention (writes oh/ol directly)
    flash_mma_kernel<<<dim3(SEQ / 64, BATCH * NHEAD), 128>>>();

    // 4) output projection
    dim3 go(D_MODEL / 256, M_TOT / 128, 1);
    gemm_mma<1><<<go, 512, G3_SMEM>>>(oh, ol,
        wh + 3 * WSTRIDE, wl + 3 * WSTRIDE,
        wh + 3 * WSTRIDE, wl + 3 * WSTRIDE,
        wh + 3 * WSTRIDE, wl + 3 * WSTRIDE,
        out, tp, M_TOT, D_MODEL, D_MODEL);
}